// round 1
// baseline (speedup 1.0000x reference)
#include <cuda_runtime.h>
#include <math.h>

// Problem constants
#define NN    4096
#define INF   4096
#define HH    1024
#define PP    256
// TAU = 0.5 -> 1/TAU = 2.0 ;  ALPHA = 0.8

// ---------------------------------------------------------------------------
// Scratch (device globals; no allocation allowed)
// ---------------------------------------------------------------------------
__device__ float g_t [NN * HH];        // GEMM temp (xW+b, h1W+b)
__device__ float g_p1[NN * HH];        // projection temps
__device__ float g_p2[NN * 512];
__device__ float g_p3[NN * 256];
__device__ float g_p4[NN * 512];
__device__ float g_n1[NN * PP];        // projected (then normalized) view 1
__device__ float g_n2[NN * PP];        // projected (then normalized) view 2
__device__ float g_R11[NN], g_B12[NN], g_R22[NN], g_B21[NN], g_dot[NN];
__device__ float g_partR[32 * NN];     // per-colblock row partials
__device__ float g_partC[32 * NN];     // per-rowblock col partials

// ---------------------------------------------------------------------------
// SGEMM: C = act(A @ B + bias)   A[M,K] lda, B[K,N] ldb, C[M,N] ldc (row-major)
// M % 128 == 0, N % 128 == 0, K % 16 == 0 (all shapes here satisfy this)
// ACT: 0 = none, 1 = leaky_relu(0.25), 2 = elu
// ---------------------------------------------------------------------------
#define BM 128
#define BN 128
#define BKK 16
#define TM 8
#define TN 8

template <int ACT>
__global__ void __launch_bounds__(256, 2)
sgemm_kernel(const float* __restrict__ A, int lda,
             const float* __restrict__ B, int ldb,
             const float* __restrict__ bias,
             float* __restrict__ C, int ldc,
             int M, int N, int K)
{
    __shared__ float As[BKK][BM + 4];
    __shared__ float Bs[BKK][BN];

    const int tid  = threadIdx.x;
    const int tx   = tid & 15;
    const int ty   = tid >> 4;
    const int brow = blockIdx.y * BM;
    const int bcol = blockIdx.x * BN;

    const int a_r = tid >> 2;          // 0..63
    const int a_c = (tid & 3) * 4;     // 0,4,8,12
    const int b_r = tid >> 5;          // 0..7
    const int b_c = (tid & 31) * 4;    // 0..124

    float acc[TM][TN];
#pragma unroll
    for (int i = 0; i < TM; i++)
#pragma unroll
        for (int j = 0; j < TN; j++) acc[i][j] = 0.f;

    for (int k0 = 0; k0 < K; k0 += BKK) {
#pragma unroll
        for (int h = 0; h < 2; ++h) {
            int r = a_r + h * 64;
            float4 v = *(const float4*)(A + (size_t)(brow + r) * lda + k0 + a_c);
            As[a_c + 0][r] = v.x; As[a_c + 1][r] = v.y;
            As[a_c + 2][r] = v.z; As[a_c + 3][r] = v.w;
        }
#pragma unroll
        for (int h = 0; h < 2; ++h) {
            int r = b_r + h * 8;
            *(float4*)(&Bs[r][b_c]) = *(const float4*)(B + (size_t)(k0 + r) * ldb + bcol + b_c);
        }
        __syncthreads();
#pragma unroll
        for (int k = 0; k < BKK; ++k) {
            float ra[TM], rb[TN];
#pragma unroll
            for (int i = 0; i < TM; i++) ra[i] = As[k][ty * TM + i];
#pragma unroll
            for (int j = 0; j < TN; j++) rb[j] = Bs[k][tx * TN + j];
#pragma unroll
            for (int i = 0; i < TM; i++)
#pragma unroll
                for (int j = 0; j < TN; j++)
                    acc[i][j] = fmaf(ra[i], rb[j], acc[i][j]);
        }
        __syncthreads();
    }

#pragma unroll
    for (int i = 0; i < TM; i++) {
        int row = brow + ty * TM + i;
#pragma unroll
        for (int j = 0; j < TN; j++) {
            int col = bcol + tx * TN + j;
            float v = acc[i][j];
            if (bias) v += bias[col];
            if (ACT == 1) v = (v > 0.f) ? v : 0.25f * v;
            else if (ACT == 2) v = (v > 0.f) ? v : expm1f(v);
            C[(size_t)row * ldc + col] = v;
        }
    }
}

// ---------------------------------------------------------------------------
// Fused exp-similarity pass: S = exp(2 * A @ B^T); emits deterministic
// per-block row-sum partials (and optional col-sum partials) without ever
// materializing S. A[Nr,K], B[Nr,K] row-major; Nr % 128 == 0, K % 16 == 0.
// partR[colblk*Nr + row], partC[rowblk*Nr + col]
// ---------------------------------------------------------------------------
__global__ void __launch_bounds__(256, 2)
expsum_kernel(const float* __restrict__ A, const float* __restrict__ B,
              float* __restrict__ partR, float* __restrict__ partC,
              int Nr, int K)
{
    __shared__ float As[BKK][BM + 4];
    __shared__ float Bs[BKK][BN + 4];
    __shared__ float cbuf[16][BN];

    const int tid  = threadIdx.x;
    const int tx   = tid & 15;
    const int ty   = tid >> 4;
    const int brow = blockIdx.y * BM;
    const int bcol = blockIdx.x * BN;

    const int a_r = tid >> 2;
    const int a_c = (tid & 3) * 4;

    float acc[TM][TN];
#pragma unroll
    for (int i = 0; i < TM; i++)
#pragma unroll
        for (int j = 0; j < TN; j++) acc[i][j] = 0.f;

    for (int k0 = 0; k0 < K; k0 += BKK) {
#pragma unroll
        for (int h = 0; h < 2; ++h) {
            int r = a_r + h * 64;
            float4 v = *(const float4*)(A + (size_t)(brow + r) * K + k0 + a_c);
            As[a_c + 0][r] = v.x; As[a_c + 1][r] = v.y;
            As[a_c + 2][r] = v.z; As[a_c + 3][r] = v.w;
            float4 w = *(const float4*)(B + (size_t)(bcol + r) * K + k0 + a_c);
            Bs[a_c + 0][r] = w.x; Bs[a_c + 1][r] = w.y;
            Bs[a_c + 2][r] = w.z; Bs[a_c + 3][r] = w.w;
        }
        __syncthreads();
#pragma unroll
        for (int k = 0; k < BKK; ++k) {
            float ra[TM], rb[TN];
#pragma unroll
            for (int i = 0; i < TM; i++) ra[i] = As[k][ty * TM + i];
#pragma unroll
            for (int j = 0; j < TN; j++) rb[j] = Bs[k][tx * TN + j];
#pragma unroll
            for (int i = 0; i < TM; i++)
#pragma unroll
                for (int j = 0; j < TN; j++)
                    acc[i][j] = fmaf(ra[i], rb[j], acc[i][j]);
        }
        __syncthreads();
    }

    // exp + per-thread row/col partials
    float rpart[TM], cpart[TN];
#pragma unroll
    for (int i = 0; i < TM; i++) rpart[i] = 0.f;
#pragma unroll
    for (int j = 0; j < TN; j++) cpart[j] = 0.f;
#pragma unroll
    for (int i = 0; i < TM; i++)
#pragma unroll
        for (int j = 0; j < TN; j++) {
            float e = expf(2.0f * acc[i][j]);
            rpart[i] += e;
            cpart[j] += e;
        }

    // row partials: reduce across the 16 tx lanes (same warp, fixed tree order)
#pragma unroll
    for (int i = 0; i < TM; i++) {
        float s = rpart[i];
#pragma unroll
        for (int o = 8; o; o >>= 1) s += __shfl_down_sync(0xffffffffu, s, o, 16);
        if (tx == 0)
            partR[(size_t)blockIdx.x * Nr + brow + ty * TM + i] = s;
    }

    // col partials: smem, reduce across ty in fixed order
#pragma unroll
    for (int j = 0; j < TN; j++) cbuf[ty][tx * TN + j] = cpart[j];
    __syncthreads();
    if (partC && tid < BN) {
        float s = 0.f;
#pragma unroll
        for (int t = 0; t < 16; t++) s += cbuf[t][tid];
        partC[(size_t)blockIdx.y * Nr + bcol + tid] = s;
    }
}

// Sum 32 partials per element (deterministic fixed order)
__global__ void reduce32_kernel(const float* __restrict__ part, float* __restrict__ out, int n)
{
    int i = blockIdx.x * blockDim.x + threadIdx.x;
    if (i < n) {
        float s = 0.f;
        for (int b = 0; b < 32; b++) s += part[(size_t)b * n + i];
        out[i] = s;
    }
}

// Row-wise L2 normalize in place: h[i,:] /= max(||h[i,:]||, 1e-12). One warp/row.
__global__ void normalize_kernel(float* __restrict__ h, int n, int p)
{
    int row  = blockIdx.x * (blockDim.x >> 5) + (threadIdx.x >> 5);
    int lane = threadIdx.x & 31;
    if (row >= n) return;
    float s = 0.f;
    for (int c = lane; c < p; c += 32) { float v = h[(size_t)row * p + c]; s += v * v; }
#pragma unroll
    for (int o = 16; o; o >>= 1) s += __shfl_xor_sync(0xffffffffu, s, o);
    float inv = 1.f / fmaxf(sqrtf(s), 1e-12f);
    for (int c = lane; c < p; c += 32) h[(size_t)row * p + c] *= inv;
}

// Row-wise dot of two matrices. One warp/row.
__global__ void rowdot_kernel(const float* __restrict__ a, const float* __restrict__ b,
                              float* __restrict__ out, int n, int p)
{
    int row  = blockIdx.x * (blockDim.x >> 5) + (threadIdx.x >> 5);
    int lane = threadIdx.x & 31;
    if (row >= n) return;
    float s = 0.f;
    for (int c = lane; c < p; c += 32) s += a[(size_t)row * p + c] * b[(size_t)row * p + c];
#pragma unroll
    for (int o = 16; o; o >>= 1) s += __shfl_xor_sync(0xffffffffu, s, o);
    if (lane == 0) out[row] = s;
}

// Final loss:
// loss = sum_i [ 0.8*log(R11+B12-e^2) + 0.2*log(R22+B21-e^2) - 2*dot_i ]
__global__ void loss_kernel(const float* __restrict__ R11, const float* __restrict__ B12,
                            const float* __restrict__ R22, const float* __restrict__ B21,
                            const float* __restrict__ dot, float* __restrict__ out, int n)
{
    __shared__ float sh[256];
    const float E2 = expf(2.0f);
    float s = 0.f;
    for (int i = threadIdx.x; i < n; i += 256) {
        s += 0.8f * logf(R11[i] + B12[i] - E2)
           + 0.2f * logf(R22[i] + B21[i] - E2)
           - 2.0f * dot[i];
    }
    sh[threadIdx.x] = s;
    __syncthreads();
    for (int o = 128; o; o >>= 1) {
        if (threadIdx.x < o) sh[threadIdx.x] += sh[threadIdx.x + o];
        __syncthreads();
    }
    if (threadIdx.x == 0) out[0] = sh[0];
}

// ---------------------------------------------------------------------------
// Host orchestration
// ---------------------------------------------------------------------------
static void launch_gemm(int act, const float* A, int lda, const float* B, int ldb,
                        const float* bias, float* C, int ldc, int M, int N, int K)
{
    dim3 grid(N / BN, M / BM), block(256);
    switch (act) {
        case 0: sgemm_kernel<0><<<grid, block>>>(A, lda, B, ldb, bias, C, ldc, M, N, K); break;
        case 1: sgemm_kernel<1><<<grid, block>>>(A, lda, B, ldb, bias, C, ldc, M, N, K); break;
        default: sgemm_kernel<2><<<grid, block>>>(A, lda, B, ldb, bias, C, ldc, M, N, K); break;
    }
}

extern "C" void kernel_launch(void* const* d_in, const int* in_sizes, int n_in,
                              void* d_out, int out_size)
{
    const float* x[2]   = { (const float*)d_in[0], (const float*)d_in[2] };
    const float* G[2]   = { (const float*)d_in[1], (const float*)d_in[3] };
    const float* Wa[2]  = { (const float*)d_in[4], (const float*)d_in[8] };
    const float* ba[2]  = { (const float*)d_in[5], (const float*)d_in[9] };
    const float* Wb[2]  = { (const float*)d_in[6], (const float*)d_in[10] };
    const float* bb[2]  = { (const float*)d_in[7], (const float*)d_in[11] };
    const float* fc1_w  = (const float*)d_in[12];
    const float* fc1_b  = (const float*)d_in[13];
    const float* fc11_w = (const float*)d_in[14];
    const float* fc11_b = (const float*)d_in[15];
    const float* fc12_w = (const float*)d_in[16];
    const float* fc12_b = (const float*)d_in[17];
    const float* fc2_w  = (const float*)d_in[18];
    const float* fc2_b  = (const float*)d_in[19];
    const float* fc3_w  = (const float*)d_in[20];
    const float* fc3_b  = (const float*)d_in[21];

    float* out = (float*)d_out;

    float *t, *p1, *p2, *p3, *p4, *n1, *n2;
    float *R11, *B12, *R22, *B21, *dot, *partR, *partC;
    cudaGetSymbolAddress((void**)&t,  g_t);
    cudaGetSymbolAddress((void**)&p1, g_p1);
    cudaGetSymbolAddress((void**)&p2, g_p2);
    cudaGetSymbolAddress((void**)&p3, g_p3);
    cudaGetSymbolAddress((void**)&p4, g_p4);
    cudaGetSymbolAddress((void**)&n1, g_n1);
    cudaGetSymbolAddress((void**)&n2, g_n2);
    cudaGetSymbolAddress((void**)&R11, g_R11);
    cudaGetSymbolAddress((void**)&B12, g_B12);
    cudaGetSymbolAddress((void**)&R22, g_R22);
    cudaGetSymbolAddress((void**)&B21, g_B21);
    cudaGetSymbolAddress((void**)&dot, g_dot);
    cudaGetSymbolAddress((void**)&partR, g_partR);
    cudaGetSymbolAddress((void**)&partC, g_partC);

    float* nrm[2] = { n1, n2 };

    for (int v = 0; v < 2; v++) {
        float* z = out + (size_t)v * NN * (2 * HH);   // [4096, 2048] slice of d_out

        // --- HGCN ---
        // T1 = x @ Wa + ba                         [4096,1024] K=4096
        launch_gemm(0, x[v], INF, Wa[v], HH, ba[v], t, HH, NN, HH, INF);
        // H1 = leaky(G @ T1) -> z[:, 0:1024]       K=4096
        launch_gemm(1, G[v], NN, t, HH, nullptr, z, 2 * HH, NN, HH, NN);
        // T2 = H1 @ Wb + bb                        K=1024 (A strided from z)
        launch_gemm(0, z, 2 * HH, Wb[v], HH, bb[v], t, HH, NN, HH, HH);
        // H2 = leaky(G @ T2) -> z[:, 1024:2048]    K=4096
        launch_gemm(1, G[v], NN, t, HH, nullptr, z + HH, 2 * HH, NN, HH, NN);

        // --- projection head ---
        launch_gemm(2, z,  2 * HH, fc1_w,  HH,  fc1_b,  p1, HH,  NN, HH,  2 * HH); // elu
        launch_gemm(2, p1, HH,     fc11_w, 512, fc11_b, p2, 512, NN, 512, HH);
        launch_gemm(2, p2, 512,    fc12_w, 256, fc12_b, p3, 256, NN, 256, 512);
        launch_gemm(2, p3, 256,    fc2_w,  512, fc2_b,  p4, 512, NN, 512, 256);
        launch_gemm(0, p4, 512,    fc3_w,  256, fc3_b,  nrm[v], 256, NN, 256, 512);
    }

    // normalize h1, h2 in place -> n1, n2
    normalize_kernel<<<NN / 8, 256>>>(n1, NN, PP);
    normalize_kernel<<<NN / 8, 256>>>(n2, NN, PP);

    dim3 egrid(NN / BN, NN / BM), eblock(256);
    // R11 = rowsum exp(2 * n1 n1^T)
    expsum_kernel<<<egrid, eblock>>>(n1, n1, partR, nullptr, NN, PP);
    reduce32_kernel<<<NN / 256, 256>>>(partR, R11, NN);
    // R22 = rowsum exp(2 * n2 n2^T)
    expsum_kernel<<<egrid, eblock>>>(n2, n2, partR, nullptr, NN, PP);
    reduce32_kernel<<<NN / 256, 256>>>(partR, R22, NN);
    // B12 = rowsum exp(2 * n1 n2^T); B21 = colsum of the same matrix
    expsum_kernel<<<egrid, eblock>>>(n1, n2, partR, partC, NN, PP);
    reduce32_kernel<<<NN / 256, 256>>>(partR, B12, NN);
    reduce32_kernel<<<NN / 256, 256>>>(partC, B21, NN);

    // diag dots (same for both loss directions)
    rowdot_kernel<<<NN / 8, 256>>>(n1, n2, dot, NN, PP);

    // final loss -> last element of d_out
    loss_kernel<<<1, 256>>>(R11, B12, R22, B21, dot, out + (out_size - 1), NN);
}

// round 2
// speedup vs baseline: 2.6972x; 2.6972x over previous
#include <cuda_runtime.h>
#include <math.h>
#include <stdint.h>

// Problem constants
#define NN    4096
#define INF   4096
#define HH    1024
#define PP    256
// TAU = 0.5 -> 1/TAU = 2.0 ;  ALPHA = 0.8

// ---------------------------------------------------------------------------
// Scratch (device globals; no allocation allowed)
// ---------------------------------------------------------------------------
__device__ float g_t [NN * HH];
__device__ float g_p1[NN * HH];
__device__ float g_p2[NN * 512];
__device__ float g_p3[NN * 256];
__device__ float g_p4[NN * 512];
__device__ float g_n1[NN * PP];
__device__ float g_n2[NN * PP];
__device__ float g_R11[NN], g_B12[NN], g_R22[NN], g_B21[NN], g_dot[NN];
__device__ float g_partR[32 * NN];
__device__ float g_partC[32 * NN];

// ---------------------------------------------------------------------------
// TF32 tensor-core GEMM: C = act(A @ B + bias)
// A[M,K] lda, B[K,N] ldb, C[M,N] ldc, all row-major fp32.
// M%128==0, N%128==0, K%32==0 (all shapes here satisfy this).
// CTA tile 128x128x32, 8 warps of 64x32, mma.sync.m16n8k8.tf32.
// ACT: 0=none, 1=leaky_relu(0.25), 2=elu
// ---------------------------------------------------------------------------
#define GBM 128
#define GBN 128
#define GBK 32
#define A_STRIDE 36           // 32 + 4 pad (conflict-free for frag reads)
#define B_STRIDE 132          // 128 + 4 pad
#define A_ELEMS (GBM * A_STRIDE)   // 4608 floats per buffer
#define B_ELEMS (GBK * B_STRIDE)   // 4224 floats per buffer
#define GEMM_SMEM_BYTES ((2 * A_ELEMS + 2 * B_ELEMS) * 4)  // 70656

__device__ __forceinline__ uint32_t f2tf32(float f) {
    uint32_t r;
    asm("cvt.rna.tf32.f32 %0, %1;" : "=r"(r) : "f"(f));
    return r;
}

__device__ __forceinline__ void mma_tf32(float* d, const uint32_t* a, const uint32_t* b) {
    asm volatile(
        "mma.sync.aligned.m16n8k8.row.col.f32.tf32.tf32.f32 "
        "{%0,%1,%2,%3}, {%4,%5,%6,%7}, {%8,%9}, {%0,%1,%2,%3};"
        : "+f"(d[0]), "+f"(d[1]), "+f"(d[2]), "+f"(d[3])
        : "r"(a[0]), "r"(a[1]), "r"(a[2]), "r"(a[3]), "r"(b[0]), "r"(b[1]));
}

__device__ __forceinline__ void cp16(float* smem_dst, const float* gmem_src) {
    uint32_t s = (uint32_t)__cvta_generic_to_shared(smem_dst);
    asm volatile("cp.async.cg.shared.global [%0], [%1], 16;" :: "r"(s), "l"(gmem_src));
}

template <int ACT>
__global__ void __launch_bounds__(256, 2)
mma_gemm_kernel(const float* __restrict__ A, int lda,
                const float* __restrict__ B, int ldb,
                const float* __restrict__ bias,
                float* __restrict__ C, int ldc,
                int M, int N, int K)
{
    extern __shared__ float sm[];
    float* sm_a = sm;                   // 2 buffers of A_ELEMS
    float* sm_b = sm + 2 * A_ELEMS;     // 2 buffers of B_ELEMS

    const int tid  = threadIdx.x;
    const int lane = tid & 31;
    const int w    = tid >> 5;
    const int wm   = w >> 2;            // 0..1
    const int wn   = w & 3;             // 0..3
    const int brow = blockIdx.y * GBM;
    const int bcol = blockIdx.x * GBN;

    float acc[4][4][4];
#pragma unroll
    for (int mi = 0; mi < 4; mi++)
#pragma unroll
        for (int ni = 0; ni < 4; ni++)
#pragma unroll
            for (int r = 0; r < 4; r++) acc[mi][ni][r] = 0.f;

    // ---- tile loader (cp.async, 16B each, 4 per matrix per thread) ----
    auto load_tile = [&](int k0, int bufIdx) {
        float* As = sm_a + bufIdx * A_ELEMS;
        float* Bs = sm_b + bufIdx * B_ELEMS;
#pragma unroll
        for (int i = 0; i < 4; i++) {
            int f = i * 256 + tid;          // 0..1023 float4 slots
            int r = f >> 3, c4 = (f & 7) * 4;
            cp16(As + r * A_STRIDE + c4, A + (size_t)(brow + r) * lda + k0 + c4);
        }
#pragma unroll
        for (int i = 0; i < 4; i++) {
            int f = i * 256 + tid;
            int r = f >> 5, c4 = (f & 31) * 4;
            cp16(Bs + r * B_STRIDE + c4, B + (size_t)(k0 + r) * ldb + bcol + c4);
        }
        asm volatile("cp.async.commit_group;");
    };

    load_tile(0, 0);

    int buf = 0;
    for (int k0 = 0; k0 < K; k0 += GBK) {
        bool has_next = (k0 + GBK < K);
        if (has_next) load_tile(k0 + GBK, buf ^ 1);

        if (has_next) asm volatile("cp.async.wait_group 1;");
        else          asm volatile("cp.async.wait_group 0;");
        __syncthreads();

        const float* As = sm_a + buf * A_ELEMS;
        const float* Bs = sm_b + buf * B_ELEMS;

#pragma unroll
        for (int ks = 0; ks < 4; ks++) {
            const int kb = ks * 8;
            uint32_t afr[4][4];
#pragma unroll
            for (int mi = 0; mi < 4; mi++) {
                int r = wm * 64 + mi * 16 + (lane >> 2);
                int c = kb + (lane & 3);
                afr[mi][0] = f2tf32(As[r * A_STRIDE + c]);
                afr[mi][1] = f2tf32(As[(r + 8) * A_STRIDE + c]);
                afr[mi][2] = f2tf32(As[r * A_STRIDE + c + 4]);
                afr[mi][3] = f2tf32(As[(r + 8) * A_STRIDE + c + 4]);
            }
            uint32_t bfr[4][2];
#pragma unroll
            for (int ni = 0; ni < 4; ni++) {
                int n = wn * 32 + ni * 8 + (lane >> 2);
                int kk = kb + (lane & 3);
                bfr[ni][0] = f2tf32(Bs[kk * B_STRIDE + n]);
                bfr[ni][1] = f2tf32(Bs[(kk + 4) * B_STRIDE + n]);
            }
#pragma unroll
            for (int mi = 0; mi < 4; mi++)
#pragma unroll
                for (int ni = 0; ni < 4; ni++)
                    mma_tf32(acc[mi][ni], afr[mi], bfr[ni]);
        }
        __syncthreads();
        buf ^= 1;
    }

    // ---- epilogue ----
#pragma unroll
    for (int mi = 0; mi < 4; mi++) {
        int r0 = brow + wm * 64 + mi * 16 + (lane >> 2);
#pragma unroll
        for (int ni = 0; ni < 4; ni++) {
            int c = bcol + wn * 32 + ni * 8 + (lane & 3) * 2;
            float bx = 0.f, by = 0.f;
            if (bias) { float2 bv = *(const float2*)(bias + c); bx = bv.x; by = bv.y; }
            float v[4];
            v[0] = acc[mi][ni][0] + bx;
            v[1] = acc[mi][ni][1] + by;
            v[2] = acc[mi][ni][2] + bx;
            v[3] = acc[mi][ni][3] + by;
#pragma unroll
            for (int r = 0; r < 4; r++) {
                if (ACT == 1) v[r] = (v[r] > 0.f) ? v[r] : 0.25f * v[r];
                else if (ACT == 2) v[r] = (v[r] > 0.f) ? v[r] : expm1f(v[r]);
            }
            *(float2*)(C + (size_t)r0 * ldc + c)       = make_float2(v[0], v[1]);
            *(float2*)(C + (size_t)(r0 + 8) * ldc + c) = make_float2(v[2], v[3]);
        }
    }
}

// ---------------------------------------------------------------------------
// Fused exp-similarity pass (fp32): row/col partial sums of exp(2*A@B^T)
// ---------------------------------------------------------------------------
#define BM 128
#define BN 128
#define BKK 16
#define TM 8
#define TN 8

__global__ void __launch_bounds__(256, 2)
expsum_kernel(const float* __restrict__ A, const float* __restrict__ B,
              float* __restrict__ partR, float* __restrict__ partC,
              int Nr, int K)
{
    __shared__ float As[BKK][BM + 4];
    __shared__ float Bs[BKK][BN + 4];
    __shared__ float cbuf[16][BN];

    const int tid  = threadIdx.x;
    const int tx   = tid & 15;
    const int ty   = tid >> 4;
    const int brow = blockIdx.y * BM;
    const int bcol = blockIdx.x * BN;

    const int a_r = tid >> 2;
    const int a_c = (tid & 3) * 4;

    float acc[TM][TN];
#pragma unroll
    for (int i = 0; i < TM; i++)
#pragma unroll
        for (int j = 0; j < TN; j++) acc[i][j] = 0.f;

    for (int k0 = 0; k0 < K; k0 += BKK) {
#pragma unroll
        for (int h = 0; h < 2; ++h) {
            int r = a_r + h * 64;
            float4 v = *(const float4*)(A + (size_t)(brow + r) * K + k0 + a_c);
            As[a_c + 0][r] = v.x; As[a_c + 1][r] = v.y;
            As[a_c + 2][r] = v.z; As[a_c + 3][r] = v.w;
            float4 w = *(const float4*)(B + (size_t)(bcol + r) * K + k0 + a_c);
            Bs[a_c + 0][r] = w.x; Bs[a_c + 1][r] = w.y;
            Bs[a_c + 2][r] = w.z; Bs[a_c + 3][r] = w.w;
        }
        __syncthreads();
#pragma unroll
        for (int k = 0; k < BKK; ++k) {
            float ra[TM], rb[TN];
#pragma unroll
            for (int i = 0; i < TM; i++) ra[i] = As[k][ty * TM + i];
#pragma unroll
            for (int j = 0; j < TN; j++) rb[j] = Bs[k][tx * TN + j];
#pragma unroll
            for (int i = 0; i < TM; i++)
#pragma unroll
                for (int j = 0; j < TN; j++)
                    acc[i][j] = fmaf(ra[i], rb[j], acc[i][j]);
        }
        __syncthreads();
    }

    float rpart[TM], cpart[TN];
#pragma unroll
    for (int i = 0; i < TM; i++) rpart[i] = 0.f;
#pragma unroll
    for (int j = 0; j < TN; j++) cpart[j] = 0.f;
#pragma unroll
    for (int i = 0; i < TM; i++)
#pragma unroll
        for (int j = 0; j < TN; j++) {
            float e = expf(2.0f * acc[i][j]);
            rpart[i] += e;
            cpart[j] += e;
        }

#pragma unroll
    for (int i = 0; i < TM; i++) {
        float s = rpart[i];
#pragma unroll
        for (int o = 8; o; o >>= 1) s += __shfl_down_sync(0xffffffffu, s, o, 16);
        if (tx == 0)
            partR[(size_t)blockIdx.x * Nr + brow + ty * TM + i] = s;
    }

#pragma unroll
    for (int j = 0; j < TN; j++) cbuf[ty][tx * TN + j] = cpart[j];
    __syncthreads();
    if (partC && tid < BN) {
        float s = 0.f;
#pragma unroll
        for (int t = 0; t < 16; t++) s += cbuf[t][tid];
        partC[(size_t)blockIdx.y * Nr + bcol + tid] = s;
    }
}

__global__ void reduce32_kernel(const float* __restrict__ part, float* __restrict__ out, int n)
{
    int i = blockIdx.x * blockDim.x + threadIdx.x;
    if (i < n) {
        float s = 0.f;
        for (int b = 0; b < 32; b++) s += part[(size_t)b * n + i];
        out[i] = s;
    }
}

__global__ void normalize_kernel(float* __restrict__ h, int n, int p)
{
    int row  = blockIdx.x * (blockDim.x >> 5) + (threadIdx.x >> 5);
    int lane = threadIdx.x & 31;
    if (row >= n) return;
    float s = 0.f;
    for (int c = lane; c < p; c += 32) { float v = h[(size_t)row * p + c]; s += v * v; }
#pragma unroll
    for (int o = 16; o; o >>= 1) s += __shfl_xor_sync(0xffffffffu, s, o);
    float inv = 1.f / fmaxf(sqrtf(s), 1e-12f);
    for (int c = lane; c < p; c += 32) h[(size_t)row * p + c] *= inv;
}

__global__ void rowdot_kernel(const float* __restrict__ a, const float* __restrict__ b,
                              float* __restrict__ out, int n, int p)
{
    int row  = blockIdx.x * (blockDim.x >> 5) + (threadIdx.x >> 5);
    int lane = threadIdx.x & 31;
    if (row >= n) return;
    float s = 0.f;
    for (int c = lane; c < p; c += 32) s += a[(size_t)row * p + c] * b[(size_t)row * p + c];
#pragma unroll
    for (int o = 16; o; o >>= 1) s += __shfl_xor_sync(0xffffffffu, s, o);
    if (lane == 0) out[row] = s;
}

__global__ void loss_kernel(const float* __restrict__ R11, const float* __restrict__ B12,
                            const float* __restrict__ R22, const float* __restrict__ B21,
                            const float* __restrict__ dot, float* __restrict__ out, int n)
{
    __shared__ float sh[256];
    const float E2 = expf(2.0f);
    float s = 0.f;
    for (int i = threadIdx.x; i < n; i += 256) {
        s += 0.8f * logf(R11[i] + B12[i] - E2)
           + 0.2f * logf(R22[i] + B21[i] - E2)
           - 2.0f * dot[i];
    }
    sh[threadIdx.x] = s;
    __syncthreads();
    for (int o = 128; o; o >>= 1) {
        if (threadIdx.x < o) sh[threadIdx.x] += sh[threadIdx.x + o];
        __syncthreads();
    }
    if (threadIdx.x == 0) out[0] = sh[0];
}

// ---------------------------------------------------------------------------
// Host orchestration
// ---------------------------------------------------------------------------
static void launch_gemm(int act, const float* A, int lda, const float* B, int ldb,
                        const float* bias, float* C, int ldc, int M, int N, int K)
{
    dim3 grid(N / GBN, M / GBM), block(256);
    switch (act) {
        case 0:
            cudaFuncSetAttribute(mma_gemm_kernel<0>, cudaFuncAttributeMaxDynamicSharedMemorySize, GEMM_SMEM_BYTES);
            mma_gemm_kernel<0><<<grid, block, GEMM_SMEM_BYTES>>>(A, lda, B, ldb, bias, C, ldc, M, N, K);
            break;
        case 1:
            cudaFuncSetAttribute(mma_gemm_kernel<1>, cudaFuncAttributeMaxDynamicSharedMemorySize, GEMM_SMEM_BYTES);
            mma_gemm_kernel<1><<<grid, block, GEMM_SMEM_BYTES>>>(A, lda, B, ldb, bias, C, ldc, M, N, K);
            break;
        default:
            cudaFuncSetAttribute(mma_gemm_kernel<2>, cudaFuncAttributeMaxDynamicSharedMemorySize, GEMM_SMEM_BYTES);
            mma_gemm_kernel<2><<<grid, block, GEMM_SMEM_BYTES>>>(A, lda, B, ldb, bias, C, ldc, M, N, K);
            break;
    }
}

extern "C" void kernel_launch(void* const* d_in, const int* in_sizes, int n_in,
                              void* d_out, int out_size)
{
    const float* x[2]   = { (const float*)d_in[0], (const float*)d_in[2] };
    const float* G[2]   = { (const float*)d_in[1], (const float*)d_in[3] };
    const float* Wa[2]  = { (const float*)d_in[4], (const float*)d_in[8] };
    const float* ba[2]  = { (const float*)d_in[5], (const float*)d_in[9] };
    const float* Wb[2]  = { (const float*)d_in[6], (const float*)d_in[10] };
    const float* bb[2]  = { (const float*)d_in[7], (const float*)d_in[11] };
    const float* fc1_w  = (const float*)d_in[12];
    const float* fc1_b  = (const float*)d_in[13];
    const float* fc11_w = (const float*)d_in[14];
    const float* fc11_b = (const float*)d_in[15];
    const float* fc12_w = (const float*)d_in[16];
    const float* fc12_b = (const float*)d_in[17];
    const float* fc2_w  = (const float*)d_in[18];
    const float* fc2_b  = (const float*)d_in[19];
    const float* fc3_w  = (const float*)d_in[20];
    const float* fc3_b  = (const float*)d_in[21];

    float* out = (float*)d_out;

    float *t, *p1, *p2, *p3, *p4, *n1, *n2;
    float *R11, *B12, *R22, *B21, *dot, *partR, *partC;
    cudaGetSymbolAddress((void**)&t,  g_t);
    cudaGetSymbolAddress((void**)&p1, g_p1);
    cudaGetSymbolAddress((void**)&p2, g_p2);
    cudaGetSymbolAddress((void**)&p3, g_p3);
    cudaGetSymbolAddress((void**)&p4, g_p4);
    cudaGetSymbolAddress((void**)&n1, g_n1);
    cudaGetSymbolAddress((void**)&n2, g_n2);
    cudaGetSymbolAddress((void**)&R11, g_R11);
    cudaGetSymbolAddress((void**)&B12, g_B12);
    cudaGetSymbolAddress((void**)&R22, g_R22);
    cudaGetSymbolAddress((void**)&B21, g_B21);
    cudaGetSymbolAddress((void**)&dot, g_dot);
    cudaGetSymbolAddress((void**)&partR, g_partR);
    cudaGetSymbolAddress((void**)&partC, g_partC);

    float* nrm[2] = { n1, n2 };

    for (int v = 0; v < 2; v++) {
        float* z = out + (size_t)v * NN * (2 * HH);   // [4096, 2048] slice of d_out

        // --- HGCN ---
        launch_gemm(0, x[v], INF, Wa[v], HH, ba[v], t, HH, NN, HH, INF);       // T1 = x@Wa+ba
        launch_gemm(1, G[v], NN, t, HH, nullptr, z, 2 * HH, NN, HH, NN);       // H1 = leaky(G@T1)
        launch_gemm(0, z, 2 * HH, Wb[v], HH, bb[v], t, HH, NN, HH, HH);        // T2 = H1@Wb+bb
        launch_gemm(1, G[v], NN, t, HH, nullptr, z + HH, 2 * HH, NN, HH, NN);  // H2 = leaky(G@T2)

        // --- projection head ---
        launch_gemm(2, z,  2 * HH, fc1_w,  HH,  fc1_b,  p1, HH,  NN, HH,  2 * HH);
        launch_gemm(2, p1, HH,     fc11_w, 512, fc11_b, p2, 512, NN, 512, HH);
        launch_gemm(2, p2, 512,    fc12_w, 256, fc12_b, p3, 256, NN, 256, 512);
        launch_gemm(2, p3, 256,    fc2_w,  512, fc2_b,  p4, 512, NN, 512, 256);
        launch_gemm(0, p4, 512,    fc3_w,  256, fc3_b,  nrm[v], 256, NN, 256, 512);
    }

    normalize_kernel<<<NN / 8, 256>>>(n1, NN, PP);
    normalize_kernel<<<NN / 8, 256>>>(n2, NN, PP);

    dim3 egrid(NN / BN, NN / BM), eblock(256);
    expsum_kernel<<<egrid, eblock>>>(n1, n1, partR, nullptr, NN, PP);
    reduce32_kernel<<<NN / 256, 256>>>(partR, R11, NN);
    expsum_kernel<<<egrid, eblock>>>(n2, n2, partR, nullptr, NN, PP);
    reduce32_kernel<<<NN / 256, 256>>>(partR, R22, NN);
    expsum_kernel<<<egrid, eblock>>>(n1, n2, partR, partC, NN, PP);
    reduce32_kernel<<<NN / 256, 256>>>(partR, B12, NN);
    reduce32_kernel<<<NN / 256, 256>>>(partC, B21, NN);

    rowdot_kernel<<<NN / 8, 256>>>(n1, n2, dot, NN, PP);

    loss_kernel<<<1, 256>>>(R11, B12, R22, B21, dot, out + (out_size - 1), NN);
}

// round 4
// speedup vs baseline: 3.2747x; 1.2141x over previous
#include <cuda_runtime.h>
#include <math.h>
#include <stdint.h>

// Problem constants
#define NN    4096
#define INF   4096
#define HH    1024
#define PP    256
// TAU = 0.5 -> 1/TAU = 2.0 ;  ALPHA = 0.8

// ---------------------------------------------------------------------------
// Scratch (device globals; no allocation allowed)
// ---------------------------------------------------------------------------
__device__ float g_t [NN * HH];
__device__ float g_p1[NN * HH];
__device__ float g_p2[NN * 512];
__device__ float g_p3[NN * 256];
__device__ float g_p4[NN * 512];
__device__ float g_n1[NN * PP];
__device__ float g_n2[NN * PP];
__device__ float g_R11[NN], g_B12[NN], g_R22[NN], g_B21[NN], g_dot[NN];
__device__ float g_partR[32 * NN];
__device__ float g_partC[32 * NN];
__device__ float g_w[13500416];          // RNA-rounded weights, packed (same layouts as inputs)
__device__ float g_rx0[NN * INF];        // RNA-rounded x1
__device__ float g_rx1[NN * INF];        // RNA-rounded x2
__device__ float g_rG0[NN * NN];         // RNA-rounded adj1
__device__ float g_rG1[NN * NN];         // RNA-rounded adj2

// offsets (floats) into g_w
#define OFF_W1A  0
#define OFF_W1B  4194304
#define OFF_W2A  5242880
#define OFF_W2B  9437184
#define OFF_FC1  10485760
#define OFF_FC11 12582912
#define OFF_FC12 13107200
#define OFF_FC2  13238272
#define OFF_FC3  13369344

// ---------------------------------------------------------------------------
// Helpers
// ---------------------------------------------------------------------------
__device__ __forceinline__ float rna_tf32(float f) {
    uint32_t r;
    asm("cvt.rna.tf32.f32 %0, %1;" : "=r"(r) : "f"(f));
    return __uint_as_float(r);
}

__device__ __forceinline__ void mma_tf32(float* d, const uint32_t* a, const uint32_t* b) {
    asm volatile(
        "mma.sync.aligned.m16n8k8.row.col.f32.tf32.tf32.f32 "
        "{%0,%1,%2,%3}, {%4,%5,%6,%7}, {%8,%9}, {%0,%1,%2,%3};"
        : "+f"(d[0]), "+f"(d[1]), "+f"(d[2]), "+f"(d[3])
        : "r"(a[0]), "r"(a[1]), "r"(a[2]), "r"(a[3]), "r"(b[0]), "r"(b[1]));
}

__device__ __forceinline__ void cp16(float* smem_dst, const float* gmem_src) {
    uint32_t s = (uint32_t)__cvta_generic_to_shared(smem_dst);
    asm volatile("cp.async.cg.shared.global [%0], [%1], 16;" :: "r"(s), "l"(gmem_src));
}

// RNA-round copy (all sizes here are multiples of 4)
__global__ void roundcpy_kernel(const float4* __restrict__ in, float4* __restrict__ out, int n4)
{
    int i = blockIdx.x * blockDim.x + threadIdx.x;
    if (i < n4) {
        float4 v = in[i];
        v.x = rna_tf32(v.x); v.y = rna_tf32(v.y);
        v.z = rna_tf32(v.z); v.w = rna_tf32(v.w);
        out[i] = v;
    }
}

// ---------------------------------------------------------------------------
// TF32 tensor-core GEMM: C = rna(act(A @ B + bias))
// A[M,K] lda, B[K,N] ldb row-major; inputs MUST already be tf32-rounded
// (fragments pass raw fp32 bits -> HW truncation is then exact).
// CTA tile 128x128x32, 8 warps of 64x32, mma.m16n8k8.
// ACT: 0=none, 1=leaky_relu(0.25), 2=elu
// ---------------------------------------------------------------------------
#define GBM 128
#define GBN 128
#define GBK 32
#define A_STRIDE 36
#define B_STRIDE 132
#define A_ELEMS (GBM * A_STRIDE)
#define B_ELEMS (GBK * B_STRIDE)
#define GEMM_SMEM_BYTES ((2 * A_ELEMS + 2 * B_ELEMS) * 4)  // 70656

template <int ACT>
__global__ void __launch_bounds__(256, 2)
mma_gemm_kernel(const float* __restrict__ A, int lda,
                const float* __restrict__ B, int ldb,
                const float* __restrict__ bias,
                float* __restrict__ C, int ldc,
                int M, int N, int K)
{
    extern __shared__ float sm[];
    float* sm_a = sm;
    float* sm_b = sm + 2 * A_ELEMS;

    const int tid  = threadIdx.x;
    const int lane = tid & 31;
    const int w    = tid >> 5;
    const int wm   = w >> 2;
    const int wn   = w & 3;
    const int brow = blockIdx.y * GBM;
    const int bcol = blockIdx.x * GBN;

    float acc[4][4][4];
#pragma unroll
    for (int mi = 0; mi < 4; mi++)
#pragma unroll
        for (int ni = 0; ni < 4; ni++)
#pragma unroll
            for (int r = 0; r < 4; r++) acc[mi][ni][r] = 0.f;

    auto load_tile = [&](int k0, int bufIdx) {
        float* As = sm_a + bufIdx * A_ELEMS;
        float* Bs = sm_b + bufIdx * B_ELEMS;
#pragma unroll
        for (int i = 0; i < 4; i++) {
            int f = i * 256 + tid;
            int r = f >> 3, c4 = (f & 7) * 4;
            cp16(As + r * A_STRIDE + c4, A + (size_t)(brow + r) * lda + k0 + c4);
        }
#pragma unroll
        for (int i = 0; i < 4; i++) {
            int f = i * 256 + tid;
            int r = f >> 5, c4 = (f & 31) * 4;
            cp16(Bs + r * B_STRIDE + c4, B + (size_t)(k0 + r) * ldb + bcol + c4);
        }
        asm volatile("cp.async.commit_group;");
    };

    load_tile(0, 0);

    int buf = 0;
    for (int k0 = 0; k0 < K; k0 += GBK) {
        bool has_next = (k0 + GBK < K);
        if (has_next) load_tile(k0 + GBK, buf ^ 1);

        if (has_next) asm volatile("cp.async.wait_group 1;");
        else          asm volatile("cp.async.wait_group 0;");
        __syncthreads();

        const float* As = sm_a + buf * A_ELEMS;
        const float* Bs = sm_b + buf * B_ELEMS;

#pragma unroll
        for (int ks = 0; ks < 4; ks++) {
            const int kb = ks * 8;
            uint32_t afr[4][4];
#pragma unroll
            for (int mi = 0; mi < 4; mi++) {
                int r = wm * 64 + mi * 16 + (lane >> 2);
                int c = kb + (lane & 3);
                afr[mi][0] = __float_as_uint(As[r * A_STRIDE + c]);
                afr[mi][1] = __float_as_uint(As[(r + 8) * A_STRIDE + c]);
                afr[mi][2] = __float_as_uint(As[r * A_STRIDE + c + 4]);
                afr[mi][3] = __float_as_uint(As[(r + 8) * A_STRIDE + c + 4]);
            }
            uint32_t bfr[4][2];
#pragma unroll
            for (int ni = 0; ni < 4; ni++) {
                int n = wn * 32 + ni * 8 + (lane >> 2);
                int kk = kb + (lane & 3);
                bfr[ni][0] = __float_as_uint(Bs[kk * B_STRIDE + n]);
                bfr[ni][1] = __float_as_uint(Bs[(kk + 4) * B_STRIDE + n]);
            }
#pragma unroll
            for (int mi = 0; mi < 4; mi++)
#pragma unroll
                for (int ni = 0; ni < 4; ni++)
                    mma_tf32(acc[mi][ni], afr[mi], bfr[ni]);
        }
        __syncthreads();
        buf ^= 1;
    }

#pragma unroll
    for (int mi = 0; mi < 4; mi++) {
        int r0 = brow + wm * 64 + mi * 16 + (lane >> 2);
#pragma unroll
        for (int ni = 0; ni < 4; ni++) {
            int c = bcol + wn * 32 + ni * 8 + (lane & 3) * 2;
            float bx = 0.f, by = 0.f;
            if (bias) { float2 bv = *(const float2*)(bias + c); bx = bv.x; by = bv.y; }
            float v[4];
            v[0] = acc[mi][ni][0] + bx;
            v[1] = acc[mi][ni][1] + by;
            v[2] = acc[mi][ni][2] + bx;
            v[3] = acc[mi][ni][3] + by;
#pragma unroll
            for (int r = 0; r < 4; r++) {
                if (ACT == 1) v[r] = (v[r] > 0.f) ? v[r] : 0.25f * v[r];
                else if (ACT == 2) v[r] = (v[r] > 0.f) ? v[r] : expm1f(v[r]);
                v[r] = rna_tf32(v[r]);   // keep downstream GEMM inputs RNA-rounded
            }
            *(float2*)(C + (size_t)r0 * ldc + c)       = make_float2(v[0], v[1]);
            *(float2*)(C + (size_t)(r0 + 8) * ldc + c) = make_float2(v[2], v[3]);
        }
    }
}

// ---------------------------------------------------------------------------
// Tensor-core exp-similarity: row/col partial sums of exp(2 * A @ B^T).
// A[Nr,K], B[Nr,K] row-major (tf32-pre-rounded). CTA 128x128, K=256.
// partR[colblk*Nr + row], partC[rowblk*Nr + col]. Deterministic reductions.
// ---------------------------------------------------------------------------
#define EX_STRIDE 36
#define EX_ELEMS (128 * EX_STRIDE)
#define EX_SMEM_BYTES (4 * EX_ELEMS * 4)   // 2 bufs x (A,B) = 73728

__global__ void __launch_bounds__(256, 2)
expsum_mma_kernel(const float* __restrict__ A, const float* __restrict__ B,
                  float* __restrict__ partR, float* __restrict__ partC,
                  int Nr, int K)
{
    extern __shared__ float sm[];
    float* sm_a = sm;                   // 2 x EX_ELEMS
    float* sm_b = sm + 2 * EX_ELEMS;    // 2 x EX_ELEMS
    __shared__ float rbuf[128][4];
    __shared__ float cbuf[128][2];

    const int tid  = threadIdx.x;
    const int lane = tid & 31;
    const int w    = tid >> 5;
    const int wm   = w >> 2;
    const int wn   = w & 3;
    const int brow = blockIdx.y * 128;
    const int bcol = blockIdx.x * 128;

    float acc[4][4][4];
#pragma unroll
    for (int mi = 0; mi < 4; mi++)
#pragma unroll
        for (int ni = 0; ni < 4; ni++)
#pragma unroll
            for (int r = 0; r < 4; r++) acc[mi][ni][r] = 0.f;

    auto load_tile = [&](int k0, int bufIdx) {
        float* As = sm_a + bufIdx * EX_ELEMS;
        float* Bs = sm_b + bufIdx * EX_ELEMS;
#pragma unroll
        for (int i = 0; i < 4; i++) {
            int f = i * 256 + tid;
            int r = f >> 3, c4 = (f & 7) * 4;
            cp16(As + r * EX_STRIDE + c4, A + (size_t)(brow + r) * K + k0 + c4);
            cp16(Bs + r * EX_STRIDE + c4, B + (size_t)(bcol + r) * K + k0 + c4);
        }
        asm volatile("cp.async.commit_group;");
    };

    load_tile(0, 0);

    int buf = 0;
    for (int k0 = 0; k0 < K; k0 += 32) {
        bool has_next = (k0 + 32 < K);
        if (has_next) load_tile(k0 + 32, buf ^ 1);
        if (has_next) asm volatile("cp.async.wait_group 1;");
        else          asm volatile("cp.async.wait_group 0;");
        __syncthreads();

        const float* As = sm_a + buf * EX_ELEMS;
        const float* Bs = sm_b + buf * EX_ELEMS;

#pragma unroll
        for (int ks = 0; ks < 4; ks++) {
            const int kb = ks * 8;
            uint32_t afr[4][4];
#pragma unroll
            for (int mi = 0; mi < 4; mi++) {
                int r = wm * 64 + mi * 16 + (lane >> 2);
                int c = kb + (lane & 3);
                afr[mi][0] = __float_as_uint(As[r * EX_STRIDE + c]);
                afr[mi][1] = __float_as_uint(As[(r + 8) * EX_STRIDE + c]);
                afr[mi][2] = __float_as_uint(As[r * EX_STRIDE + c + 4]);
                afr[mi][3] = __float_as_uint(As[(r + 8) * EX_STRIDE + c + 4]);
            }
            uint32_t bfr[4][2];
#pragma unroll
            for (int ni = 0; ni < 4; ni++) {
                int n = wn * 32 + ni * 8 + (lane >> 2);
                int kk = kb + (lane & 3);
                bfr[ni][0] = __float_as_uint(Bs[n * EX_STRIDE + kk]);
                bfr[ni][1] = __float_as_uint(Bs[n * EX_STRIDE + kk + 4]);
            }
#pragma unroll
            for (int mi = 0; mi < 4; mi++)
#pragma unroll
                for (int ni = 0; ni < 4; ni++)
                    mma_tf32(acc[mi][ni], afr[mi], bfr[ni]);
        }
        __syncthreads();
        buf ^= 1;
    }

    // exp + fragment-level partial sums
    float rsum[4][2], csum[4][2];
#pragma unroll
    for (int i = 0; i < 4; i++) { rsum[i][0] = rsum[i][1] = 0.f; csum[i][0] = csum[i][1] = 0.f; }
#pragma unroll
    for (int mi = 0; mi < 4; mi++)
#pragma unroll
        for (int ni = 0; ni < 4; ni++) {
            float e0 = __expf(2.0f * acc[mi][ni][0]);
            float e1 = __expf(2.0f * acc[mi][ni][1]);
            float e2 = __expf(2.0f * acc[mi][ni][2]);
            float e3 = __expf(2.0f * acc[mi][ni][3]);
            rsum[mi][0] += e0 + e1;
            rsum[mi][1] += e2 + e3;
            csum[ni][0] += e0 + e2;
            csum[ni][1] += e1 + e3;
        }

    // row sums: reduce across the 4 lanes of each quad (fixed order)
#pragma unroll
    for (int mi = 0; mi < 4; mi++)
#pragma unroll
        for (int h = 0; h < 2; h++) {
            float s = rsum[mi][h];
            s += __shfl_down_sync(0xffffffffu, s, 2, 4);
            s += __shfl_down_sync(0xffffffffu, s, 1, 4);
            if ((lane & 3) == 0)
                rbuf[wm * 64 + mi * 16 + h * 8 + (lane >> 2)][wn] = s;
        }

    // col sums: reduce across the 8 quads (fixed order)
#pragma unroll
    for (int ni = 0; ni < 4; ni++)
#pragma unroll
        for (int h = 0; h < 2; h++) {
            float s = csum[ni][h];
            s += __shfl_down_sync(0xffffffffu, s, 16);
            s += __shfl_down_sync(0xffffffffu, s, 8);
            s += __shfl_down_sync(0xffffffffu, s, 4);
            if (lane < 4)
                cbuf[wn * 32 + ni * 8 + lane * 2 + h][wm] = s;
        }

    __syncthreads();
    if (tid < 128) {
        float rs = rbuf[tid][0] + rbuf[tid][1] + rbuf[tid][2] + rbuf[tid][3];
        partR[(size_t)blockIdx.x * Nr + brow + tid] = rs;
        if (partC) {
            float cs = cbuf[tid][0] + cbuf[tid][1];
            partC[(size_t)blockIdx.y * Nr + bcol + tid] = cs;
        }
    }
}

// ---------------------------------------------------------------------------
// Small kernels
// ---------------------------------------------------------------------------
__global__ void reduce32_kernel(const float* __restrict__ part, float* __restrict__ out, int n)
{
    int i = blockIdx.x * blockDim.x + threadIdx.x;
    if (i < n) {
        float s = 0.f;
        for (int b = 0; b < 32; b++) s += part[(size_t)b * n + i];
        out[i] = s;
    }
}

__global__ void normalize_kernel(float* __restrict__ h, int n, int p)
{
    int row  = blockIdx.x * (blockDim.x >> 5) + (threadIdx.x >> 5);
    int lane = threadIdx.x & 31;
    if (row >= n) return;
    float s = 0.f;
    for (int c = lane; c < p; c += 32) { float v = h[(size_t)row * p + c]; s += v * v; }
#pragma unroll
    for (int o = 16; o; o >>= 1) s += __shfl_xor_sync(0xffffffffu, s, o);
    float inv = 1.f / fmaxf(sqrtf(s), 1e-12f);
    for (int c = lane; c < p; c += 32)
        h[(size_t)row * p + c] = rna_tf32(h[(size_t)row * p + c] * inv);
}

__global__ void rowdot_kernel(const float* __restrict__ a, const float* __restrict__ b,
                              float* __restrict__ out, int n, int p)
{
    int row  = blockIdx.x * (blockDim.x >> 5) + (threadIdx.x >> 5);
    int lane = threadIdx.x & 31;
    if (row >= n) return;
    float s = 0.f;
    for (int c = lane; c < p; c += 32) s += a[(size_t)row * p + c] * b[(size_t)row * p + c];
#pragma unroll
    for (int o = 16; o; o >>= 1) s += __shfl_xor_sync(0xffffffffu, s, o);
    if (lane == 0) out[row] = s;
}

__global__ void loss_kernel(const float* __restrict__ R11, const float* __restrict__ B12,
                            const float* __restrict__ R22, const float* __restrict__ B21,
                            const float* __restrict__ dot, float* __restrict__ out, int n)
{
    __shared__ float sh[256];
    const float E2 = expf(2.0f);
    float s = 0.f;
    for (int i = threadIdx.x; i < n; i += 256) {
        s += 0.8f * logf(R11[i] + B12[i] - E2)
           + 0.2f * logf(R22[i] + B21[i] - E2)
           - 2.0f * dot[i];
    }
    sh[threadIdx.x] = s;
    __syncthreads();
    for (int o = 128; o; o >>= 1) {
        if (threadIdx.x < o) sh[threadIdx.x] += sh[threadIdx.x + o];
        __syncthreads();
    }
    if (threadIdx.x == 0) out[0] = sh[0];
}

// ---------------------------------------------------------------------------
// Host orchestration
// ---------------------------------------------------------------------------
static void launch_gemm(int act, const float* A, int lda, const float* B, int ldb,
                        const float* bias, float* C, int ldc, int M, int N, int K)
{
    dim3 grid(N / GBN, M / GBM), block(256);
    switch (act) {
        case 0:
            cudaFuncSetAttribute(mma_gemm_kernel<0>, cudaFuncAttributeMaxDynamicSharedMemorySize, GEMM_SMEM_BYTES);
            mma_gemm_kernel<0><<<grid, block, GEMM_SMEM_BYTES>>>(A, lda, B, ldb, bias, C, ldc, M, N, K);
            break;
        case 1:
            cudaFuncSetAttribute(mma_gemm_kernel<1>, cudaFuncAttributeMaxDynamicSharedMemorySize, GEMM_SMEM_BYTES);
            mma_gemm_kernel<1><<<grid, block, GEMM_SMEM_BYTES>>>(A, lda, B, ldb, bias, C, ldc, M, N, K);
            break;
        default:
            cudaFuncSetAttribute(mma_gemm_kernel<2>, cudaFuncAttributeMaxDynamicSharedMemorySize, GEMM_SMEM_BYTES);
            mma_gemm_kernel<2><<<grid, block, GEMM_SMEM_BYTES>>>(A, lda, B, ldb, bias, C, ldc, M, N, K);
            break;
    }
}

static void launch_round(const float* src, float* dst, int n)
{
    int n4 = n / 4;
    roundcpy_kernel<<<(n4 + 255) / 256, 256>>>((const float4*)src, (float4*)dst, n4);
}

extern "C" void kernel_launch(void* const* d_in, const int* in_sizes, int n_in,
                              void* d_out, int out_size)
{
    const float* x[2]   = { (const float*)d_in[0], (const float*)d_in[2] };
    const float* G[2]   = { (const float*)d_in[1], (const float*)d_in[3] };
    const float* Wa[2]  = { (const float*)d_in[4], (const float*)d_in[8] };
    const float* ba[2]  = { (const float*)d_in[5], (const float*)d_in[9] };
    const float* Wb[2]  = { (const float*)d_in[6], (const float*)d_in[10] };
    const float* bb[2]  = { (const float*)d_in[7], (const float*)d_in[11] };
    const float* fc1_w  = (const float*)d_in[12];
    const float* fc1_b  = (const float*)d_in[13];
    const float* fc11_w = (const float*)d_in[14];
    const float* fc11_b = (const float*)d_in[15];
    const float* fc12_w = (const float*)d_in[16];
    const float* fc12_b = (const float*)d_in[17];
    const float* fc2_w  = (const float*)d_in[18];
    const float* fc2_b  = (const float*)d_in[19];
    const float* fc3_w  = (const float*)d_in[20];
    const float* fc3_b  = (const float*)d_in[21];

    float* out = (float*)d_out;

    float *t, *p1, *p2, *p3, *p4, *n1, *n2, *wr, *rx0, *rx1, *rG0, *rG1;
    float *R11, *B12, *R22, *B21, *dot, *partR, *partC;
    cudaGetSymbolAddress((void**)&t,   g_t);
    cudaGetSymbolAddress((void**)&p1,  g_p1);
    cudaGetSymbolAddress((void**)&p2,  g_p2);
    cudaGetSymbolAddress((void**)&p3,  g_p3);
    cudaGetSymbolAddress((void**)&p4,  g_p4);
    cudaGetSymbolAddress((void**)&n1,  g_n1);
    cudaGetSymbolAddress((void**)&n2,  g_n2);
    cudaGetSymbolAddress((void**)&wr,  g_w);
    cudaGetSymbolAddress((void**)&rx0, g_rx0);
    cudaGetSymbolAddress((void**)&rx1, g_rx1);
    cudaGetSymbolAddress((void**)&rG0, g_rG0);
    cudaGetSymbolAddress((void**)&rG1, g_rG1);
    cudaGetSymbolAddress((void**)&R11, g_R11);
    cudaGetSymbolAddress((void**)&B12, g_B12);
    cudaGetSymbolAddress((void**)&R22, g_R22);
    cudaGetSymbolAddress((void**)&B21, g_B21);
    cudaGetSymbolAddress((void**)&dot, g_dot);
    cudaGetSymbolAddress((void**)&partR, g_partR);
    cudaGetSymbolAddress((void**)&partC, g_partC);

    // --- RNA-round all GEMM inputs once ---
    launch_round(x[0], rx0, NN * INF);
    launch_round(x[1], rx1, NN * INF);
    launch_round(G[0], rG0, NN * NN);
    launch_round(G[1], rG1, NN * NN);
    launch_round(Wa[0],  wr + OFF_W1A,  INF * HH);
    launch_round(Wb[0],  wr + OFF_W1B,  HH * HH);
    launch_round(Wa[1],  wr + OFF_W2A,  INF * HH);
    launch_round(Wb[1],  wr + OFF_W2B,  HH * HH);
    launch_round(fc1_w,  wr + OFF_FC1,  2 * HH * HH);
    launch_round(fc11_w, wr + OFF_FC11, HH * 512);
    launch_round(fc12_w, wr + OFF_FC12, 512 * 256);
    launch_round(fc2_w,  wr + OFF_FC2,  256 * 512);
    launch_round(fc3_w,  wr + OFF_FC3,  512 * 256);

    const float* rx[2]  = { rx0, rx1 };
    const float* rG[2]  = { rG0, rG1 };
    const float* WaR[2] = { wr + OFF_W1A, wr + OFF_W2A };
    const float* WbR[2] = { wr + OFF_W1B, wr + OFF_W2B };
    float* nrm[2] = { n1, n2 };

    for (int v = 0; v < 2; v++) {
        float* z = out + (size_t)v * NN * (2 * HH);   // [4096,2048] slice of d_out

        // --- HGCN ---
        launch_gemm(0, rx[v], INF, WaR[v], HH, ba[v], t, HH, NN, HH, INF);      // T1 = x@Wa+ba
        launch_gemm(1, rG[v], NN, t, HH, nullptr, z, 2 * HH, NN, HH, NN);       // H1 = leaky(G@T1)
        launch_gemm(0, z, 2 * HH, WbR[v], HH, bb[v], t, HH, NN, HH, HH);        // T2 = H1@Wb+bb
        launch_gemm(1, rG[v], NN, t, HH, nullptr, z + HH, 2 * HH, NN, HH, NN);  // H2 = leaky(G@T2)

        // --- projection head ---
        launch_gemm(2, z,  2 * HH, wr + OFF_FC1,  HH,  fc1_b,  p1, HH,  NN, HH,  2 * HH);
        launch_gemm(2, p1, HH,     wr + OFF_FC11, 512, fc11_b, p2, 512, NN, 512, HH);
        launch_gemm(2, p2, 512,    wr + OFF_FC12, 256, fc12_b, p3, 256, NN, 256, 512);
        launch_gemm(2, p3, 256,    wr + OFF_FC2,  512, fc2_b,  p4, 512, NN, 512, 256);
        launch_gemm(0, p4, 512,    wr + OFF_FC3,  256, fc3_b,  nrm[v], 256, NN, 256, 512);
    }

    normalize_kernel<<<NN / 8, 256>>>(n1, NN, PP);
    normalize_kernel<<<NN / 8, 256>>>(n2, NN, PP);

    dim3 egrid(32, 32), eblock(256);
    cudaFuncSetAttribute(expsum_mma_kernel, cudaFuncAttributeMaxDynamicSharedMemorySize, EX_SMEM_BYTES);
    expsum_mma_kernel<<<egrid, eblock, EX_SMEM_BYTES>>>(n1, n1, partR, nullptr, NN, PP);
    reduce32_kernel<<<NN / 256, 256>>>(partR, R11, NN);
    expsum_mma_kernel<<<egrid, eblock, EX_SMEM_BYTES>>>(n2, n2, partR, nullptr, NN, PP);
    reduce32_kernel<<<NN / 256, 256>>>(partR, R22, NN);
    expsum_mma_kernel<<<egrid, eblock, EX_SMEM_BYTES>>>(n1, n2, partR, partC, NN, PP);
    reduce32_kernel<<<NN / 256, 256>>>(partR, B12, NN);
    reduce32_kernel<<<NN / 256, 256>>>(partC, B21, NN);

    rowdot_kernel<<<NN / 8, 256>>>(n1, n2, dot, NN, PP);

    loss_kernel<<<1, 256>>>(R11, B12, R22, B21, dot, out + (out_size - 1), NN);
}

// round 6
// speedup vs baseline: 5.8824x; 1.7963x over previous
#include <cuda_runtime.h>
#include <cuda_fp16.h>
#include <math.h>
#include <stdint.h>

// Problem constants
#define NN    4096
#define INF   4096
#define HH    1024
#define PP    256
// TAU = 0.5 -> 1/TAU = 2.0 ;  ALPHA = 0.8

// ---------------------------------------------------------------------------
// Scratch (device globals; no allocation allowed)
// ---------------------------------------------------------------------------
__device__ __half g_hx [2 * NN * INF];     // fp16 x1,x2
__device__ __half g_hG [2 * NN * NN];      // fp16 G1,G2 (pre-scaled by 4096)
__device__ __half g_hw [13500416];         // fp16 transposed weights [N,K], packed
__device__ __half g_th [NN * HH];          // fp16 GEMM temp T
__device__ __half g_tTh[NN * HH];          // fp16 T transposed [1024,4096]
__device__ __half g_zh [NN * 2 * HH];      // fp16 copy of z (per view, reused)
__device__ __half g_p1h[NN * HH];
__device__ __half g_p2h[NN * 512];
__device__ __half g_p3h[NN * 256];
__device__ __half g_p4h[NN * 512];
__device__ __half g_n1h[NN * PP];
__device__ __half g_n2h[NN * PP];
__device__ float  g_n1[NN * PP];
__device__ float  g_n2[NN * PP];
__device__ float  g_R11[NN], g_B12[NN], g_R22[NN], g_B21[NN], g_dot[NN];
__device__ float  g_partR[32 * NN];
__device__ float  g_partC[32 * NN];

// offsets (halves) into g_hw  (transposed: [N,K])
#define OFF_W1A  0
#define OFF_W1B  4194304
#define OFF_W2A  5242880
#define OFF_W2B  9437184
#define OFF_FC1  10485760
#define OFF_FC11 12582912
#define OFF_FC12 13107200
#define OFF_FC2  13238272
#define OFF_FC3  13369344

// ---------------------------------------------------------------------------
// Helpers
// ---------------------------------------------------------------------------
__device__ __forceinline__ uint32_t h2u(__half2 h) {
    union { __half2 h; uint32_t u; } cvt;
    cvt.h = h;
    return cvt.u;
}

__device__ __forceinline__ void mma_fp16(float* d, const uint32_t* a, const uint32_t* b) {
    asm volatile(
        "mma.sync.aligned.m16n8k16.row.col.f32.f16.f16.f32 "
        "{%0,%1,%2,%3}, {%4,%5,%6,%7}, {%8,%9}, {%0,%1,%2,%3};"
        : "+f"(d[0]), "+f"(d[1]), "+f"(d[2]), "+f"(d[3])
        : "r"(a[0]), "r"(a[1]), "r"(a[2]), "r"(a[3]), "r"(b[0]), "r"(b[1]));
}

__device__ __forceinline__ void cp16(const __half* smem_dst, const __half* gmem_src) {
    uint32_t s = (uint32_t)__cvta_generic_to_shared(smem_dst);
    asm volatile("cp.async.cg.shared.global [%0], [%1], 16;" :: "r"(s), "l"(gmem_src));
}

// fp32 -> fp16 with scale (n % 4 == 0)
__global__ void cvt_half_kernel(const float4* __restrict__ in, uint2* __restrict__ out,
                                float scale, int n4)
{
    int i = blockIdx.x * blockDim.x + threadIdx.x;
    if (i < n4) {
        float4 v = in[i];
        __half2 lo = __floats2half2_rn(v.x * scale, v.y * scale);
        __half2 hi = __floats2half2_rn(v.z * scale, v.w * scale);
        out[i] = make_uint2(h2u(lo), h2u(hi));
    }
}

// fp32 [rows,cols] -> fp16 transposed [cols,rows]
__global__ void cvtT_kernel(const float* __restrict__ src, __half* __restrict__ dst,
                            int rows, int cols)
{
    __shared__ __half tile[32][33];
    int c0 = blockIdx.x * 32, r0 = blockIdx.y * 32;
    int x = threadIdx.x, y = threadIdx.y;  // 32x8
#pragma unroll
    for (int i = 0; i < 32; i += 8)
        tile[y + i][x] = __float2half_rn(src[(size_t)(r0 + y + i) * cols + c0 + x]);
    __syncthreads();
#pragma unroll
    for (int i = 0; i < 32; i += 8)
        dst[(size_t)(c0 + y + i) * rows + r0 + x] = tile[x][y + i];
}

// fp16 [rows,cols] -> fp16 transposed [cols,rows]
__global__ void transposeh_kernel(const __half* __restrict__ src, __half* __restrict__ dst,
                                  int rows, int cols)
{
    __shared__ __half tile[32][33];
    int c0 = blockIdx.x * 32, r0 = blockIdx.y * 32;
    int x = threadIdx.x, y = threadIdx.y;  // 32x8
#pragma unroll
    for (int i = 0; i < 32; i += 8)
        tile[y + i][x] = src[(size_t)(r0 + y + i) * cols + c0 + x];
    __syncthreads();
#pragma unroll
    for (int i = 0; i < 32; i += 8)
        dst[(size_t)(c0 + y + i) * rows + r0 + x] = tile[x][y + i];
}

// ---------------------------------------------------------------------------
// FP16 tensor-core GEMM: acc = A @ B^T (fp32 accum); out = act(acc*postScale + bias)
// A[M,K] fp16 row-major (lda), BT[N,K] fp16 row-major (ldb).
// Writes C32 (fp32) and/or C16 (fp16), both with leading dim ldc.
// CTA tile 128x128x64, 8 warps of 64x32, mma.m16n8k16.
// ACT: 0=none, 1=leaky_relu(0.25), 2=elu
// ---------------------------------------------------------------------------
#define SK 72                         // smem k-stride in halves (64 + 8)
#define TILE_HALVES (128 * SK)        // 9216 halves = 18432 B
#define HG_SMEM_BYTES (4 * TILE_HALVES * 2)   // 2 bufs x (A,B) = 73728

template <int ACT>
__global__ void __launch_bounds__(256, 2)
hgemm_kernel(const __half* __restrict__ A, int lda,
             const __half* __restrict__ BT, int ldb,
             const float* __restrict__ bias, float postScale,
             float* __restrict__ C32, __half* __restrict__ C16, int ldc,
             int K)
{
    extern __shared__ __half smh[];
    __half* sm_a = smh;                    // 2 x TILE_HALVES
    __half* sm_b = smh + 2 * TILE_HALVES;  // 2 x TILE_HALVES

    const int tid  = threadIdx.x;
    const int lane = tid & 31;
    const int w    = tid >> 5;
    const int wm   = w >> 2;               // 0..1
    const int wn   = w & 3;                // 0..3
    const int brow = blockIdx.y * 128;
    const int bcol = blockIdx.x * 128;

    float acc[4][4][4];
#pragma unroll
    for (int mi = 0; mi < 4; mi++)
#pragma unroll
        for (int ni = 0; ni < 4; ni++)
#pragma unroll
            for (int r = 0; r < 4; r++) acc[mi][ni][r] = 0.f;

    // loader: 1024 chunks of 16B (8 halves) per matrix; 4 per thread
    auto load_tile = [&](int k0, int bufIdx) {
        __half* As = sm_a + bufIdx * TILE_HALVES;
        __half* Bs = sm_b + bufIdx * TILE_HALVES;
#pragma unroll
        for (int i = 0; i < 4; i++) {
            int f = i * 256 + tid;
            int r = f >> 3, c8 = (f & 7) * 8;
            cp16(As + r * SK + c8, A + (size_t)(brow + r) * lda + k0 + c8);
            cp16(Bs + r * SK + c8, BT + (size_t)(bcol + r) * ldb + k0 + c8);
        }
        asm volatile("cp.async.commit_group;");
    };

    load_tile(0, 0);

    int buf = 0;
    for (int k0 = 0; k0 < K; k0 += 64) {
        bool has_next = (k0 + 64 < K);
        if (has_next) load_tile(k0 + 64, buf ^ 1);
        if (has_next) asm volatile("cp.async.wait_group 1;");
        else          asm volatile("cp.async.wait_group 0;");
        __syncthreads();

        const __half* As = sm_a + buf * TILE_HALVES;
        const __half* Bs = sm_b + buf * TILE_HALVES;

#pragma unroll
        for (int ks = 0; ks < 4; ks++) {
            const int c2 = ks * 16 + 2 * (lane & 3);
            uint32_t afr[4][4];
#pragma unroll
            for (int mi = 0; mi < 4; mi++) {
                int r = wm * 64 + mi * 16 + (lane >> 2);
                afr[mi][0] = *(const uint32_t*)(As + r * SK + c2);
                afr[mi][1] = *(const uint32_t*)(As + (r + 8) * SK + c2);
                afr[mi][2] = *(const uint32_t*)(As + r * SK + c2 + 8);
                afr[mi][3] = *(const uint32_t*)(As + (r + 8) * SK + c2 + 8);
            }
            uint32_t bfr[4][2];
#pragma unroll
            for (int ni = 0; ni < 4; ni++) {
                int n = wn * 32 + ni * 8 + (lane >> 2);
                bfr[ni][0] = *(const uint32_t*)(Bs + n * SK + c2);
                bfr[ni][1] = *(const uint32_t*)(Bs + n * SK + c2 + 8);
            }
#pragma unroll
            for (int mi = 0; mi < 4; mi++)
#pragma unroll
                for (int ni = 0; ni < 4; ni++)
                    mma_fp16(acc[mi][ni], afr[mi], bfr[ni]);
        }
        __syncthreads();
        buf ^= 1;
    }

    // epilogue
#pragma unroll
    for (int mi = 0; mi < 4; mi++) {
        int r0 = brow + wm * 64 + mi * 16 + (lane >> 2);
#pragma unroll
        for (int ni = 0; ni < 4; ni++) {
            int c = bcol + wn * 32 + ni * 8 + (lane & 3) * 2;
            float bx = 0.f, by = 0.f;
            if (bias) { float2 bv = *(const float2*)(bias + c); bx = bv.x; by = bv.y; }
            float v[4];
            v[0] = fmaf(acc[mi][ni][0], postScale, bx);
            v[1] = fmaf(acc[mi][ni][1], postScale, by);
            v[2] = fmaf(acc[mi][ni][2], postScale, bx);
            v[3] = fmaf(acc[mi][ni][3], postScale, by);
#pragma unroll
            for (int r = 0; r < 4; r++) {
                if (ACT == 1) v[r] = (v[r] > 0.f) ? v[r] : 0.25f * v[r];
                else if (ACT == 2) v[r] = (v[r] > 0.f) ? v[r] : expm1f(v[r]);
            }
            if (C32) {
                *(float2*)(C32 + (size_t)r0 * ldc + c)       = make_float2(v[0], v[1]);
                *(float2*)(C32 + (size_t)(r0 + 8) * ldc + c) = make_float2(v[2], v[3]);
            }
            if (C16) {
                *(uint32_t*)(C16 + (size_t)r0 * ldc + c)       = h2u(__floats2half2_rn(v[0], v[1]));
                *(uint32_t*)(C16 + (size_t)(r0 + 8) * ldc + c) = h2u(__floats2half2_rn(v[2], v[3]));
            }
        }
    }
}

// ---------------------------------------------------------------------------
// FP16 exp-similarity: row/col partial sums of exp(2 * A @ B^T), fp32 accum.
// A[Nr,K], B[Nr,K] fp16 row-major. CTA 128x128, K=256.
// partR[colblk*Nr + row], partC[rowblk*Nr + col]. Deterministic reductions.
// ---------------------------------------------------------------------------
__global__ void __launch_bounds__(256, 2)
expsum_h_kernel(const __half* __restrict__ A, const __half* __restrict__ B,
                float* __restrict__ partR, float* __restrict__ partC,
                int Nr, int K)
{
    extern __shared__ __half smh[];
    __half* sm_a = smh;
    __half* sm_b = smh + 2 * TILE_HALVES;
    __shared__ float rbuf[128][4];
    __shared__ float cbuf[128][2];

    const int tid  = threadIdx.x;
    const int lane = tid & 31;
    const int w    = tid >> 5;
    const int wm   = w >> 2;
    const int wn   = w & 3;
    const int brow = blockIdx.y * 128;
    const int bcol = blockIdx.x * 128;

    float acc[4][4][4];
#pragma unroll
    for (int mi = 0; mi < 4; mi++)
#pragma unroll
        for (int ni = 0; ni < 4; ni++)
#pragma unroll
            for (int r = 0; r < 4; r++) acc[mi][ni][r] = 0.f;

    auto load_tile = [&](int k0, int bufIdx) {
        __half* As = sm_a + bufIdx * TILE_HALVES;
        __half* Bs = sm_b + bufIdx * TILE_HALVES;
#pragma unroll
        for (int i = 0; i < 4; i++) {
            int f = i * 256 + tid;
            int r = f >> 3, c8 = (f & 7) * 8;
            cp16(As + r * SK + c8, A + (size_t)(brow + r) * K + k0 + c8);
            cp16(Bs + r * SK + c8, B + (size_t)(bcol + r) * K + k0 + c8);
        }
        asm volatile("cp.async.commit_group;");
    };

    load_tile(0, 0);

    int buf = 0;
    for (int k0 = 0; k0 < K; k0 += 64) {
        bool has_next = (k0 + 64 < K);
        if (has_next) load_tile(k0 + 64, buf ^ 1);
        if (has_next) asm volatile("cp.async.wait_group 1;");
        else          asm volatile("cp.async.wait_group 0;");
        __syncthreads();

        const __half* As = sm_a + buf * TILE_HALVES;
        const __half* Bs = sm_b + buf * TILE_HALVES;

#pragma unroll
        for (int ks = 0; ks < 4; ks++) {
            const int c2 = ks * 16 + 2 * (lane & 3);
            uint32_t afr[4][4];
#pragma unroll
            for (int mi = 0; mi < 4; mi++) {
                int r = wm * 64 + mi * 16 + (lane >> 2);
                afr[mi][0] = *(const uint32_t*)(As + r * SK + c2);
                afr[mi][1] = *(const uint32_t*)(As + (r + 8) * SK + c2);
                afr[mi][2] = *(const uint32_t*)(As + r * SK + c2 + 8);
                afr[mi][3] = *(const uint32_t*)(As + (r + 8) * SK + c2 + 8);
            }
            uint32_t bfr[4][2];
#pragma unroll
            for (int ni = 0; ni < 4; ni++) {
                int n = wn * 32 + ni * 8 + (lane >> 2);
                bfr[ni][0] = *(const uint32_t*)(Bs + n * SK + c2);
                bfr[ni][1] = *(const uint32_t*)(Bs + n * SK + c2 + 8);
            }
#pragma unroll
            for (int mi = 0; mi < 4; mi++)
#pragma unroll
                for (int ni = 0; ni < 4; ni++)
                    mma_fp16(acc[mi][ni], afr[mi], bfr[ni]);
        }
        __syncthreads();
        buf ^= 1;
    }

    // exp + fragment-level partial sums
    float rsum[4][2], csum[4][2];
#pragma unroll
    for (int i = 0; i < 4; i++) { rsum[i][0] = rsum[i][1] = 0.f; csum[i][0] = csum[i][1] = 0.f; }
#pragma unroll
    for (int mi = 0; mi < 4; mi++)
#pragma unroll
        for (int ni = 0; ni < 4; ni++) {
            float e0 = __expf(2.0f * acc[mi][ni][0]);
            float e1 = __expf(2.0f * acc[mi][ni][1]);
            float e2 = __expf(2.0f * acc[mi][ni][2]);
            float e3 = __expf(2.0f * acc[mi][ni][3]);
            rsum[mi][0] += e0 + e1;
            rsum[mi][1] += e2 + e3;
            csum[ni][0] += e0 + e2;
            csum[ni][1] += e1 + e3;
        }

    // row sums: reduce across the 4 lanes of each quad (fixed order)
#pragma unroll
    for (int mi = 0; mi < 4; mi++)
#pragma unroll
        for (int h = 0; h < 2; h++) {
            float s = rsum[mi][h];
            s += __shfl_down_sync(0xffffffffu, s, 2, 4);
            s += __shfl_down_sync(0xffffffffu, s, 1, 4);
            if ((lane & 3) == 0)
                rbuf[wm * 64 + mi * 16 + h * 8 + (lane >> 2)][wn] = s;
        }

    // col sums: reduce across the 8 quads (fixed order)
#pragma unroll
    for (int ni = 0; ni < 4; ni++)
#pragma unroll
        for (int h = 0; h < 2; h++) {
            float s = csum[ni][h];
            s += __shfl_down_sync(0xffffffffu, s, 16);
            s += __shfl_down_sync(0xffffffffu, s, 8);
            s += __shfl_down_sync(0xffffffffu, s, 4);
            if (lane < 4)
                cbuf[wn * 32 + ni * 8 + lane * 2 + h][wm] = s;
        }

    __syncthreads();
    if (tid < 128) {
        float rs = rbuf[tid][0] + rbuf[tid][1] + rbuf[tid][2] + rbuf[tid][3];
        partR[(size_t)blockIdx.x * Nr + brow + tid] = rs;
        if (partC) {
            float cs = cbuf[tid][0] + cbuf[tid][1];
            partC[(size_t)blockIdx.y * Nr + bcol + tid] = cs;
        }
    }
}

// ---------------------------------------------------------------------------
// Small kernels
// ---------------------------------------------------------------------------
__global__ void reduce32_kernel(const float* __restrict__ part, float* __restrict__ out, int n)
{
    int i = blockIdx.x * blockDim.x + threadIdx.x;
    if (i < n) {
        float s = 0.f;
        for (int b = 0; b < 32; b++) s += part[(size_t)b * n + i];
        out[i] = s;
    }
}

// L2 normalize rows of h (fp32, in place) + write fp16 copy
__global__ void normalize_kernel(float* __restrict__ h, __half* __restrict__ hh, int n, int p)
{
    int row  = blockIdx.x * (blockDim.x >> 5) + (threadIdx.x >> 5);
    int lane = threadIdx.x & 31;
    if (row >= n) return;
    float s = 0.f;
    for (int c = lane; c < p; c += 32) { float v = h[(size_t)row * p + c]; s += v * v; }
#pragma unroll
    for (int o = 16; o; o >>= 1) s += __shfl_xor_sync(0xffffffffu, s, o);
    float inv = 1.f / fmaxf(sqrtf(s), 1e-12f);
    for (int c = lane; c < p; c += 32) {
        float v = h[(size_t)row * p + c] * inv;
        h[(size_t)row * p + c] = v;
        hh[(size_t)row * p + c] = __float2half_rn(v);
    }
}

__global__ void rowdot_kernel(const float* __restrict__ a, const float* __restrict__ b,
                              float* __restrict__ out, int n, int p)
{
    int row  = blockIdx.x * (blockDim.x >> 5) + (threadIdx.x >> 5);
    int lane = threadIdx.x & 31;
    if (row >= n) return;
    float s = 0.f;
    for (int c = lane; c < p; c += 32) s += a[(size_t)row * p + c] * b[(size_t)row * p + c];
#pragma unroll
    for (int o = 16; o; o >>= 1) s += __shfl_xor_sync(0xffffffffu, s, o);
    if (lane == 0) out[row] = s;
}

__global__ void loss_kernel(const float* __restrict__ R11, const float* __restrict__ B12,
                            const float* __restrict__ R22, const float* __restrict__ B21,
                            const float* __restrict__ dot, float* __restrict__ out, int n)
{
    __shared__ float sh[256];
    const float E2 = expf(2.0f);
    float s = 0.f;
    for (int i = threadIdx.x; i < n; i += 256) {
        s += 0.8f * logf(R11[i] + B12[i] - E2)
           + 0.2f * logf(R22[i] + B21[i] - E2)
           - 2.0f * dot[i];
    }
    sh[threadIdx.x] = s;
    __syncthreads();
    for (int o = 128; o; o >>= 1) {
        if (threadIdx.x < o) sh[threadIdx.x] += sh[threadIdx.x + o];
        __syncthreads();
    }
    if (threadIdx.x == 0) out[0] = sh[0];
}

// ---------------------------------------------------------------------------
// Host orchestration
// ---------------------------------------------------------------------------
static void launch_hgemm(int act, const __half* A, int lda, const __half* BT, int ldb,
                         const float* bias, float postScale,
                         float* C32, __half* C16, int ldc, int M, int N, int K)
{
    dim3 grid(N / 128, M / 128), block(256);
    switch (act) {
        case 0:
            cudaFuncSetAttribute(hgemm_kernel<0>, cudaFuncAttributeMaxDynamicSharedMemorySize, HG_SMEM_BYTES);
            hgemm_kernel<0><<<grid, block, HG_SMEM_BYTES>>>(A, lda, BT, ldb, bias, postScale, C32, C16, ldc, K);
            break;
        case 1:
            cudaFuncSetAttribute(hgemm_kernel<1>, cudaFuncAttributeMaxDynamicSharedMemorySize, HG_SMEM_BYTES);
            hgemm_kernel<1><<<grid, block, HG_SMEM_BYTES>>>(A, lda, BT, ldb, bias, postScale, C32, C16, ldc, K);
            break;
        default:
            cudaFuncSetAttribute(hgemm_kernel<2>, cudaFuncAttributeMaxDynamicSharedMemorySize, HG_SMEM_BYTES);
            hgemm_kernel<2><<<grid, block, HG_SMEM_BYTES>>>(A, lda, BT, ldb, bias, postScale, C32, C16, ldc, K);
            break;
    }
}

static void launch_cvt(const float* src, __half* dst, float scale, int n)
{
    int n4 = n / 4;
    cvt_half_kernel<<<(n4 + 255) / 256, 256>>>((const float4*)src, (uint2*)dst, scale, n4);
}

static void launch_cvtT(const float* src, __half* dst, int rows, int cols)
{
    dim3 grid(cols / 32, rows / 32), block(32, 8);
    cvtT_kernel<<<grid, block>>>(src, dst, rows, cols);
}

extern "C" void kernel_launch(void* const* d_in, const int* in_sizes, int n_in,
                              void* d_out, int out_size)
{
    const float* x[2]   = { (const float*)d_in[0], (const float*)d_in[2] };
    const float* G[2]   = { (const float*)d_in[1], (const float*)d_in[3] };
    const float* Wa[2]  = { (const float*)d_in[4], (const float*)d_in[8] };
    const float* ba[2]  = { (const float*)d_in[5], (const float*)d_in[9] };
    const float* Wb[2]  = { (const float*)d_in[6], (const float*)d_in[10] };
    const float* bb[2]  = { (const float*)d_in[7], (const float*)d_in[11] };
    const float* fc1_w  = (const float*)d_in[12];
    const float* fc1_b  = (const float*)d_in[13];
    const float* fc11_w = (const float*)d_in[14];
    const float* fc11_b = (const float*)d_in[15];
    const float* fc12_w = (const float*)d_in[16];
    const float* fc12_b = (const float*)d_in[17];
    const float* fc2_w  = (const float*)d_in[18];
    const float* fc2_b  = (const float*)d_in[19];
    const float* fc3_w  = (const float*)d_in[20];
    const float* fc3_b  = (const float*)d_in[21];

    float* out = (float*)d_out;

    __half *hx, *hG, *hw, *th, *tTh, *zh, *p1h, *p2h, *p3h, *p4h, *n1h, *n2h;
    float *n1, *n2, *R11, *B12, *R22, *B21, *dot, *partR, *partC;
    cudaGetSymbolAddress((void**)&hx,  g_hx);
    cudaGetSymbolAddress((void**)&hG,  g_hG);
    cudaGetSymbolAddress((void**)&hw,  g_hw);
    cudaGetSymbolAddress((void**)&th,  g_th);
    cudaGetSymbolAddress((void**)&tTh, g_tTh);
    cudaGetSymbolAddress((void**)&zh,  g_zh);
    cudaGetSymbolAddress((void**)&p1h, g_p1h);
    cudaGetSymbolAddress((void**)&p2h, g_p2h);
    cudaGetSymbolAddress((void**)&p3h, g_p3h);
    cudaGetSymbolAddress((void**)&p4h, g_p4h);
    cudaGetSymbolAddress((void**)&n1h, g_n1h);
    cudaGetSymbolAddress((void**)&n2h, g_n2h);
    cudaGetSymbolAddress((void**)&n1,  g_n1);
    cudaGetSymbolAddress((void**)&n2,  g_n2);
    cudaGetSymbolAddress((void**)&R11, g_R11);
    cudaGetSymbolAddress((void**)&B12, g_B12);
    cudaGetSymbolAddress((void**)&R22, g_R22);
    cudaGetSymbolAddress((void**)&B21, g_B21);
    cudaGetSymbolAddress((void**)&dot, g_dot);
    cudaGetSymbolAddress((void**)&partR, g_partR);
    cudaGetSymbolAddress((void**)&partC, g_partC);

    // --- convert inputs to fp16 (G pre-scaled by 4096 to stay in normal range) ---
    launch_cvt(x[0], hx,                1.0f,    NN * INF);
    launch_cvt(x[1], hx + NN * INF,     1.0f,    NN * INF);
    launch_cvt(G[0], hG,                4096.0f, NN * NN);
    launch_cvt(G[1], hG + NN * NN,      4096.0f, NN * NN);
    // --- transpose+convert weights: [K,N] fp32 -> [N,K] fp16 ---
    launch_cvtT(Wa[0],  hw + OFF_W1A,  INF, HH);
    launch_cvtT(Wb[0],  hw + OFF_W1B,  HH,  HH);
    launch_cvtT(Wa[1],  hw + OFF_W2A,  INF, HH);
    launch_cvtT(Wb[1],  hw + OFF_W2B,  HH,  HH);
    launch_cvtT(fc1_w,  hw + OFF_FC1,  2 * HH, HH);
    launch_cvtT(fc11_w, hw + OFF_FC11, HH,  512);
    launch_cvtT(fc12_w, hw + OFF_FC12, 512, 256);
    launch_cvtT(fc2_w,  hw + OFF_FC2,  256, 512);
    launch_cvtT(fc3_w,  hw + OFF_FC3,  512, 256);

    const __half* hxv[2] = { hx, hx + NN * INF };
    const __half* hGv[2] = { hG, hG + NN * NN };
    const __half* WaT[2] = { hw + OFF_W1A, hw + OFF_W2A };
    const __half* WbT[2] = { hw + OFF_W1B, hw + OFF_W2B };
    float* nrm[2] = { n1, n2 };
    const float INV = 1.0f / 4096.0f;

    for (int v = 0; v < 2; v++) {
        float* z = out + (size_t)v * NN * (2 * HH);   // [4096,2048] slice of d_out

        // --- HGCN ---
        // T1 = x@Wa + ba (fp16)
        launch_hgemm(0, hxv[v], INF, WaT[v], INF, ba[v], 1.f, nullptr, th, HH, NN, HH, INF);
        transposeh_kernel<<<dim3(HH / 32, NN / 32), dim3(32, 8)>>>(th, tTh, NN, HH);
        // H1 = leaky(G@T1): fp32 -> z, fp16 -> zh
        launch_hgemm(1, hGv[v], NN, tTh, NN, nullptr, INV, z, zh, 2 * HH, NN, HH, NN);
        // T2 = H1@Wb + bb
        launch_hgemm(0, zh, 2 * HH, WbT[v], HH, bb[v], 1.f, nullptr, th, HH, NN, HH, HH);
        transposeh_kernel<<<dim3(HH / 32, NN / 32), dim3(32, 8)>>>(th, tTh, NN, HH);
        // H2 = leaky(G@T2)
        launch_hgemm(1, hGv[v], NN, tTh, NN, nullptr, INV, z + HH, zh + HH, 2 * HH, NN, HH, NN);

        // --- projection head ---
        launch_hgemm(2, zh,  2 * HH, hw + OFF_FC1,  2 * HH, fc1_b,  1.f, nullptr, p1h, HH,  NN, HH,  2 * HH);
        launch_hgemm(2, p1h, HH,     hw + OFF_FC11, HH,     fc11_b, 1.f, nullptr, p2h, 512, NN, 512, HH);
        launch_hgemm(2, p2h, 512,    hw + OFF_FC12, 512,    fc12_b, 1.f, nullptr, p3h, 256, NN, 256, 512);
        launch_hgemm(2, p3h, 256,    hw + OFF_FC2,  256,    fc2_b,  1.f, nullptr, p4h, 512, NN, 512, 256);
        launch_hgemm(0, p4h, 512,    hw + OFF_FC3,  512,    fc3_b,  1.f, nrm[v], nullptr, 256, NN, 256, 512);
    }

    normalize_kernel<<<NN / 8, 256>>>(n1, n1h, NN, PP);
    normalize_kernel<<<NN / 8, 256>>>(n2, n2h, NN, PP);

    dim3 egrid(32, 32), eblock(256);
    cudaFuncSetAttribute(expsum_h_kernel, cudaFuncAttributeMaxDynamicSharedMemorySize, HG_SMEM_BYTES);
    expsum_h_kernel<<<egrid, eblock, HG_SMEM_BYTES>>>(n1h, n1h, partR, nullptr, NN, PP);
    reduce32_kernel<<<NN / 256, 256>>>(partR, R11, NN);
    expsum_h_kernel<<<egrid, eblock, HG_SMEM_BYTES>>>(n2h, n2h, partR, nullptr, NN, PP);
    reduce32_kernel<<<NN / 256, 256>>>(partR, R22, NN);
    expsum_h_kernel<<<egrid, eblock, HG_SMEM_BYTES>>>(n1h, n2h, partR, partC, NN, PP);
    reduce32_kernel<<<NN / 256, 256>>>(partR, B12, NN);
    reduce32_kernel<<<NN / 256, 256>>>(partC, B21, NN);

    rowdot_kernel<<<NN / 8, 256>>>(n1, n2, dot, NN, PP);

    loss_kernel<<<1, 256>>>(R11, B12, R22, B21, dot, out + (out_size - 1), NN);
}

// round 7
// speedup vs baseline: 6.5980x; 1.1217x over previous
#include <cuda_runtime.h>
#include <cuda_fp16.h>
#include <math.h>
#include <stdint.h>

// Problem constants
#define NN    4096
#define INF   4096
#define HH    1024
#define PP    256
// TAU = 0.5 -> 1/TAU = 2.0 ;  ALPHA = 0.8

// ---------------------------------------------------------------------------
// Scratch (device globals; no allocation allowed)
// ---------------------------------------------------------------------------
__device__ __half g_hx [2 * NN * INF];     // fp16 x1,x2
__device__ __half g_hG [2 * NN * NN];      // fp16 G1,G2 (pre-scaled by 4096)
__device__ __half g_hw [13500416];         // fp16 transposed weights [N,K], packed
__device__ __half g_th [2 * NN * HH];      // fp16 GEMM temp T (both views)
__device__ __half g_tTh[2 * NN * HH];      // fp16 T transposed (both views)
__device__ __half g_zh [2 * NN * 2 * HH];  // fp16 copy of z (both views)
__device__ __half g_p1h[2 * NN * HH];
__device__ __half g_p2h[2 * NN * 512];
__device__ __half g_p3h[2 * NN * 256];
__device__ __half g_p4h[2 * NN * 512];
__device__ __half g_n1h[NN * PP];
__device__ __half g_n2h[NN * PP];
__device__ float  g_n1[NN * PP];
__device__ float  g_n2[NN * PP];
__device__ float  g_R11[NN], g_B12[NN], g_R22[NN], g_B21[NN], g_dot[NN];
__device__ float  g_partR[32 * NN];
__device__ float  g_partC[32 * NN];

// offsets (halves) into g_hw  (transposed: [N,K])
#define OFF_W1A  0
#define OFF_W1B  4194304
#define OFF_W2A  5242880
#define OFF_W2B  9437184
#define OFF_FC1  10485760
#define OFF_FC11 12582912
#define OFF_FC12 13107200
#define OFF_FC2  13238272
#define OFF_FC3  13369344

// ---------------------------------------------------------------------------
// Helpers
// ---------------------------------------------------------------------------
__device__ __forceinline__ uint32_t h2u(__half2 h) {
    union { __half2 h; uint32_t u; } cvt;
    cvt.h = h;
    return cvt.u;
}

__device__ __forceinline__ void mma_fp16(float* d, const uint32_t* a, uint32_t b0, uint32_t b1) {
    asm volatile(
        "mma.sync.aligned.m16n8k16.row.col.f32.f16.f16.f32 "
        "{%0,%1,%2,%3}, {%4,%5,%6,%7}, {%8,%9}, {%0,%1,%2,%3};"
        : "+f"(d[0]), "+f"(d[1]), "+f"(d[2]), "+f"(d[3])
        : "r"(a[0]), "r"(a[1]), "r"(a[2]), "r"(a[3]), "r"(b0), "r"(b1));
}

__device__ __forceinline__ void ldsm4(uint32_t* r, uint32_t a) {
    asm volatile("ldmatrix.sync.aligned.m8n8.x4.shared.b16 {%0,%1,%2,%3}, [%4];"
                 : "=r"(r[0]), "=r"(r[1]), "=r"(r[2]), "=r"(r[3]) : "r"(a));
}

__device__ __forceinline__ void cp16(const __half* smem_dst, const __half* gmem_src) {
    uint32_t s = (uint32_t)__cvta_generic_to_shared(smem_dst);
    asm volatile("cp.async.cg.shared.global [%0], [%1], 16;" :: "r"(s), "l"(gmem_src));
}

// fp32 -> fp16 with scale (n % 4 == 0)
__global__ void cvt_half_kernel(const float4* __restrict__ in, uint2* __restrict__ out,
                                float scale, int n4)
{
    int i = blockIdx.x * blockDim.x + threadIdx.x;
    if (i < n4) {
        float4 v = in[i];
        __half2 lo = __floats2half2_rn(v.x * scale, v.y * scale);
        __half2 hi = __floats2half2_rn(v.z * scale, v.w * scale);
        out[i] = make_uint2(h2u(lo), h2u(hi));
    }
}

// fp32 [rows,cols] -> fp16 transposed [cols,rows]
__global__ void cvtT_kernel(const float* __restrict__ src, __half* __restrict__ dst,
                            int rows, int cols)
{
    __shared__ __half tile[32][33];
    int c0 = blockIdx.x * 32, r0 = blockIdx.y * 32;
    int x = threadIdx.x, y = threadIdx.y;  // 32x8
#pragma unroll
    for (int i = 0; i < 32; i += 8)
        tile[y + i][x] = __float2half_rn(src[(size_t)(r0 + y + i) * cols + c0 + x]);
    __syncthreads();
#pragma unroll
    for (int i = 0; i < 32; i += 8)
        dst[(size_t)(c0 + y + i) * rows + r0 + x] = tile[x][y + i];
}

// fp16 [rows,cols] -> fp16 transposed [cols,rows]; batched over z
__global__ void transposeh_kernel(const __half* __restrict__ src0, __half* __restrict__ dst0,
                                  int rows, int cols)
{
    __shared__ __half tile[32][33];
    const __half* src = src0 + (size_t)blockIdx.z * rows * cols;
    __half* dst = dst0 + (size_t)blockIdx.z * rows * cols;
    int c0 = blockIdx.x * 32, r0 = blockIdx.y * 32;
    int x = threadIdx.x, y = threadIdx.y;  // 32x8
#pragma unroll
    for (int i = 0; i < 32; i += 8)
        tile[y + i][x] = src[(size_t)(r0 + y + i) * cols + c0 + x];
    __syncthreads();
#pragma unroll
    for (int i = 0; i < 32; i += 8)
        dst[(size_t)(c0 + y + i) * rows + r0 + x] = tile[x][y + i];
}

// ---------------------------------------------------------------------------
// FP16 tensor-core GEMM, dual-view (blockIdx.z): acc = A @ B^T (fp32 accum);
// out = act(acc*postScale + bias).  A[M,K] fp16 (lda), BT[N,K] fp16 (ldb).
// ldmatrix fragment loads, 3-stage cp.async pipeline.
// ACT: 0=none, 1=leaky_relu(0.25), 2=elu
// ---------------------------------------------------------------------------
struct GemmView {
    const __half* A;
    const __half* BT;
    const float*  bias;
    float*        C32;
    __half*       C16;
};

#define SK 72                          // smem k-stride in halves (64 + 8)
#define TILE_HALVES (128 * SK)         // 9216 halves = 18432 B
#define NSTAGE 3
#define HG_SMEM_BYTES (NSTAGE * 2 * TILE_HALVES * 2)   // 110592

template <int ACT>
__global__ void __launch_bounds__(256, 2)
hgemm_kernel(GemmView v0, GemmView v1, int lda, int ldb,
             float postScale, int ldc, int K)
{
    const GemmView V = blockIdx.z ? v1 : v0;
    extern __shared__ __half smh[];
    const uint32_t sbase = (uint32_t)__cvta_generic_to_shared(smh);

    const int tid  = threadIdx.x;
    const int lane = tid & 31;
    const int w    = tid >> 5;
    const int wm   = w >> 2;               // 0..1
    const int wn   = w & 3;                // 0..3
    const int brow = blockIdx.y * 128;
    const int bcol = blockIdx.x * 128;

    float acc[4][4][4];
#pragma unroll
    for (int mi = 0; mi < 4; mi++)
#pragma unroll
        for (int ni = 0; ni < 4; ni++)
#pragma unroll
            for (int r = 0; r < 4; r++) acc[mi][ni][r] = 0.f;

    auto load_tile = [&](int s) {
        int k0 = s * 64;
        __half* As = smh + (s % NSTAGE) * 2 * TILE_HALVES;
        __half* Bs = As + TILE_HALVES;
#pragma unroll
        for (int i = 0; i < 4; i++) {
            int f = i * 256 + tid;
            int r = f >> 3, c8 = (f & 7) * 8;
            cp16(As + r * SK + c8, V.A + (size_t)(brow + r) * lda + k0 + c8);
            cp16(Bs + r * SK + c8, V.BT + (size_t)(bcol + r) * ldb + k0 + c8);
        }
        asm volatile("cp.async.commit_group;");
    };

    const int nst = K >> 6;
    load_tile(0);
    load_tile(1);

    // per-thread ldmatrix address components
    const int a_row = wm * 64 + (lane & 15);
    const int a_koff = (lane >> 4) * 8;
    const int b_row = wn * 32 + ((lane >> 4) * 8) + (lane & 7);
    const int b_koff = ((lane >> 3) & 1) * 8;

    for (int s = 0; s < nst; s++) {
        if (s + 1 < nst) asm volatile("cp.async.wait_group 1;");
        else             asm volatile("cp.async.wait_group 0;");
        __syncthreads();
        if (s + 2 < nst) load_tile(s + 2);

        const uint32_t aab = sbase + ((s % NSTAGE) * 2 * TILE_HALVES) * 2;
        const uint32_t bbb = aab + TILE_HALVES * 2;

#pragma unroll
        for (int ks = 0; ks < 4; ks++) {
            const int kb = ks * 16;
            uint32_t afr[4][4];
#pragma unroll
            for (int mi = 0; mi < 4; mi++)
                ldsm4(afr[mi], aab + (((a_row + mi * 16) * SK) + kb + a_koff) * 2);
            uint32_t bq[2][4];
#pragma unroll
            for (int p = 0; p < 2; p++)
                ldsm4(bq[p], bbb + (((b_row + p * 16) * SK) + kb + b_koff) * 2);
#pragma unroll
            for (int mi = 0; mi < 4; mi++)
#pragma unroll
                for (int ni = 0; ni < 4; ni++)
                    mma_fp16(acc[mi][ni], afr[mi], bq[ni >> 1][(ni & 1) * 2], bq[ni >> 1][(ni & 1) * 2 + 1]);
        }
        __syncthreads();
    }

    // epilogue
#pragma unroll
    for (int mi = 0; mi < 4; mi++) {
        int r0 = brow + wm * 64 + mi * 16 + (lane >> 2);
#pragma unroll
        for (int ni = 0; ni < 4; ni++) {
            int c = bcol + wn * 32 + ni * 8 + (lane & 3) * 2;
            float bx = 0.f, by = 0.f;
            if (V.bias) { float2 bv = *(const float2*)(V.bias + c); bx = bv.x; by = bv.y; }
            float v[4];
            v[0] = fmaf(acc[mi][ni][0], postScale, bx);
            v[1] = fmaf(acc[mi][ni][1], postScale, by);
            v[2] = fmaf(acc[mi][ni][2], postScale, bx);
            v[3] = fmaf(acc[mi][ni][3], postScale, by);
#pragma unroll
            for (int r = 0; r < 4; r++) {
                if (ACT == 1) v[r] = (v[r] > 0.f) ? v[r] : 0.25f * v[r];
                else if (ACT == 2) v[r] = (v[r] > 0.f) ? v[r] : expm1f(v[r]);
            }
            if (V.C32) {
                *(float2*)(V.C32 + (size_t)r0 * ldc + c)       = make_float2(v[0], v[1]);
                *(float2*)(V.C32 + (size_t)(r0 + 8) * ldc + c) = make_float2(v[2], v[3]);
            }
            if (V.C16) {
                *(uint32_t*)(V.C16 + (size_t)r0 * ldc + c)       = h2u(__floats2half2_rn(v[0], v[1]));
                *(uint32_t*)(V.C16 + (size_t)(r0 + 8) * ldc + c) = h2u(__floats2half2_rn(v[2], v[3]));
            }
        }
    }
}

// ---------------------------------------------------------------------------
// FP16 exp-similarity: row/col partial sums of exp(2 * A @ B^T), fp32 accum.
// A[Nr,K], B[Nr,K] fp16 row-major. CTA 128x128, K=256. ldmatrix loads.
// partR[colblk*Nr + row], partC[rowblk*Nr + col]. Deterministic reductions.
// ---------------------------------------------------------------------------
__global__ void __launch_bounds__(256, 2)
expsum_h_kernel(const __half* __restrict__ A, const __half* __restrict__ B,
                float* __restrict__ partR, float* __restrict__ partC,
                int Nr, int K)
{
    extern __shared__ __half smh[];
    const uint32_t sbase = (uint32_t)__cvta_generic_to_shared(smh);
    __shared__ float rbuf[128][4];
    __shared__ float cbuf[128][2];

    const int tid  = threadIdx.x;
    const int lane = tid & 31;
    const int w    = tid >> 5;
    const int wm   = w >> 2;
    const int wn   = w & 3;
    const int brow = blockIdx.y * 128;
    const int bcol = blockIdx.x * 128;

    float acc[4][4][4];
#pragma unroll
    for (int mi = 0; mi < 4; mi++)
#pragma unroll
        for (int ni = 0; ni < 4; ni++)
#pragma unroll
            for (int r = 0; r < 4; r++) acc[mi][ni][r] = 0.f;

    auto load_tile = [&](int s) {
        int k0 = s * 64;
        __half* As = smh + (s % NSTAGE) * 2 * TILE_HALVES;
        __half* Bs = As + TILE_HALVES;
#pragma unroll
        for (int i = 0; i < 4; i++) {
            int f = i * 256 + tid;
            int r = f >> 3, c8 = (f & 7) * 8;
            cp16(As + r * SK + c8, A + (size_t)(brow + r) * K + k0 + c8);
            cp16(Bs + r * SK + c8, B + (size_t)(bcol + r) * K + k0 + c8);
        }
        asm volatile("cp.async.commit_group;");
    };

    const int nst = K >> 6;
    load_tile(0);
    load_tile(1);

    const int a_row = wm * 64 + (lane & 15);
    const int a_koff = (lane >> 4) * 8;
    const int b_row = wn * 32 + ((lane >> 4) * 8) + (lane & 7);
    const int b_koff = ((lane >> 3) & 1) * 8;

    for (int s = 0; s < nst; s++) {
        if (s + 1 < nst) asm volatile("cp.async.wait_group 1;");
        else             asm volatile("cp.async.wait_group 0;");
        __syncthreads();
        if (s + 2 < nst) load_tile(s + 2);

        const uint32_t aab = sbase + ((s % NSTAGE) * 2 * TILE_HALVES) * 2;
        const uint32_t bbb = aab + TILE_HALVES * 2;

#pragma unroll
        for (int ks = 0; ks < 4; ks++) {
            const int kb = ks * 16;
            uint32_t afr[4][4];
#pragma unroll
            for (int mi = 0; mi < 4; mi++)
                ldsm4(afr[mi], aab + (((a_row + mi * 16) * SK) + kb + a_koff) * 2);
            uint32_t bq[2][4];
#pragma unroll
            for (int p = 0; p < 2; p++)
                ldsm4(bq[p], bbb + (((b_row + p * 16) * SK) + kb + b_koff) * 2);
#pragma unroll
            for (int mi = 0; mi < 4; mi++)
#pragma unroll
                for (int ni = 0; ni < 4; ni++)
                    mma_fp16(acc[mi][ni], afr[mi], bq[ni >> 1][(ni & 1) * 2], bq[ni >> 1][(ni & 1) * 2 + 1]);
        }
        __syncthreads();
    }

    // exp + fragment-level partial sums
    float rsum[4][2], csum[4][2];
#pragma unroll
    for (int i = 0; i < 4; i++) { rsum[i][0] = rsum[i][1] = 0.f; csum[i][0] = csum[i][1] = 0.f; }
#pragma unroll
    for (int mi = 0; mi < 4; mi++)
#pragma unroll
        for (int ni = 0; ni < 4; ni++) {
            float e0 = __expf(2.0f * acc[mi][ni][0]);
            float e1 = __expf(2.0f * acc[mi][ni][1]);
            float e2 = __expf(2.0f * acc[mi][ni][2]);
            float e3 = __expf(2.0f * acc[mi][ni][3]);
            rsum[mi][0] += e0 + e1;
            rsum[mi][1] += e2 + e3;
            csum[ni][0] += e0 + e2;
            csum[ni][1] += e1 + e3;
        }

    // row sums: reduce across the 4 lanes of each quad (fixed order)
#pragma unroll
    for (int mi = 0; mi < 4; mi++)
#pragma unroll
        for (int h = 0; h < 2; h++) {
            float s = rsum[mi][h];
            s += __shfl_down_sync(0xffffffffu, s, 2, 4);
            s += __shfl_down_sync(0xffffffffu, s, 1, 4);
            if ((lane & 3) == 0)
                rbuf[wm * 64 + mi * 16 + h * 8 + (lane >> 2)][wn] = s;
        }

    // col sums: reduce across the 8 quads (fixed order)
#pragma unroll
    for (int ni = 0; ni < 4; ni++)
#pragma unroll
        for (int h = 0; h < 2; h++) {
            float s = csum[ni][h];
            s += __shfl_down_sync(0xffffffffu, s, 16);
            s += __shfl_down_sync(0xffffffffu, s, 8);
            s += __shfl_down_sync(0xffffffffu, s, 4);
            if (lane < 4)
                cbuf[wn * 32 + ni * 8 + lane * 2 + h][wm] = s;
        }

    __syncthreads();
    if (tid < 128) {
        float rs = rbuf[tid][0] + rbuf[tid][1] + rbuf[tid][2] + rbuf[tid][3];
        partR[(size_t)blockIdx.x * Nr + brow + tid] = rs;
        if (partC) {
            float cs = cbuf[tid][0] + cbuf[tid][1];
            partC[(size_t)blockIdx.y * Nr + bcol + tid] = cs;
        }
    }
}

// ---------------------------------------------------------------------------
// Small kernels
// ---------------------------------------------------------------------------
__global__ void reduce32_kernel(const float* __restrict__ part, float* __restrict__ out, int n)
{
    int i = blockIdx.x * blockDim.x + threadIdx.x;
    if (i < n) {
        float s = 0.f;
        for (int b = 0; b < 32; b++) s += part[(size_t)b * n + i];
        out[i] = s;
    }
}

// L2 normalize rows of h (fp32, in place) + write fp16 copy
__global__ void normalize_kernel(float* __restrict__ h, __half* __restrict__ hh, int n, int p)
{
    int row  = blockIdx.x * (blockDim.x >> 5) + (threadIdx.x >> 5);
    int lane = threadIdx.x & 31;
    if (row >= n) return;
    float s = 0.f;
    for (int c = lane; c < p; c += 32) { float v = h[(size_t)row * p + c]; s += v * v; }
#pragma unroll
    for (int o = 16; o; o >>= 1) s += __shfl_xor_sync(0xffffffffu, s, o);
    float inv = 1.f / fmaxf(sqrtf(s), 1e-12f);
    for (int c = lane; c < p; c += 32) {
        float v = h[(size_t)row * p + c] * inv;
        h[(size_t)row * p + c] = v;
        hh[(size_t)row * p + c] = __float2half_rn(v);
    }
}

__global__ void rowdot_kernel(const float* __restrict__ a, const float* __restrict__ b,
                              float* __restrict__ out, int n, int p)
{
    int row  = blockIdx.x * (blockDim.x >> 5) + (threadIdx.x >> 5);
    int lane = threadIdx.x & 31;
    if (row >= n) return;
    float s = 0.f;
    for (int c = lane; c < p; c += 32) s += a[(size_t)row * p + c] * b[(size_t)row * p + c];
#pragma unroll
    for (int o = 16; o; o >>= 1) s += __shfl_xor_sync(0xffffffffu, s, o);
    if (lane == 0) out[row] = s;
}

__global__ void loss_kernel(const float* __restrict__ R11, const float* __restrict__ B12,
                            const float* __restrict__ R22, const float* __restrict__ B21,
                            const float* __restrict__ dot, float* __restrict__ out, int n)
{
    __shared__ float sh[256];
    const float E2 = expf(2.0f);
    float s = 0.f;
    for (int i = threadIdx.x; i < n; i += 256) {
        s += 0.8f * logf(R11[i] + B12[i] - E2)
           + 0.2f * logf(R22[i] + B21[i] - E2)
           - 2.0f * dot[i];
    }
    sh[threadIdx.x] = s;
    __syncthreads();
    for (int o = 128; o; o >>= 1) {
        if (threadIdx.x < o) sh[threadIdx.x] += sh[threadIdx.x + o];
        __syncthreads();
    }
    if (threadIdx.x == 0) out[0] = sh[0];
}

// ---------------------------------------------------------------------------
// Host orchestration
// ---------------------------------------------------------------------------
static void launch_hgemm(int act, GemmView v0, GemmView v1, int lda, int ldb,
                         float postScale, int ldc, int M, int N, int K)
{
    dim3 grid(N / 128, M / 128, 2), block(256);
    switch (act) {
        case 0:
            cudaFuncSetAttribute(hgemm_kernel<0>, cudaFuncAttributeMaxDynamicSharedMemorySize, HG_SMEM_BYTES);
            hgemm_kernel<0><<<grid, block, HG_SMEM_BYTES>>>(v0, v1, lda, ldb, postScale, ldc, K);
            break;
        case 1:
            cudaFuncSetAttribute(hgemm_kernel<1>, cudaFuncAttributeMaxDynamicSharedMemorySize, HG_SMEM_BYTES);
            hgemm_kernel<1><<<grid, block, HG_SMEM_BYTES>>>(v0, v1, lda, ldb, postScale, ldc, K);
            break;
        default:
            cudaFuncSetAttribute(hgemm_kernel<2>, cudaFuncAttributeMaxDynamicSharedMemorySize, HG_SMEM_BYTES);
            hgemm_kernel<2><<<grid, block, HG_SMEM_BYTES>>>(v0, v1, lda, ldb, postScale, ldc, K);
            break;
    }
}

static void launch_cvt(const float* src, __half* dst, float scale, int n)
{
    int n4 = n / 4;
    cvt_half_kernel<<<(n4 + 255) / 256, 256>>>((const float4*)src, (uint2*)dst, scale, n4);
}

static void launch_cvtT(const float* src, __half* dst, int rows, int cols)
{
    dim3 grid(cols / 32, rows / 32), block(32, 8);
    cvtT_kernel<<<grid, block>>>(src, dst, rows, cols);
}

extern "C" void kernel_launch(void* const* d_in, const int* in_sizes, int n_in,
                              void* d_out, int out_size)
{
    const float* x[2]   = { (const float*)d_in[0], (const float*)d_in[2] };
    const float* G[2]   = { (const float*)d_in[1], (const float*)d_in[3] };
    const float* Wa[2]  = { (const float*)d_in[4], (const float*)d_in[8] };
    const float* ba[2]  = { (const float*)d_in[5], (const float*)d_in[9] };
    const float* Wb[2]  = { (const float*)d_in[6], (const float*)d_in[10] };
    const float* bb[2]  = { (const float*)d_in[7], (const float*)d_in[11] };
    const float* fc1_w  = (const float*)d_in[12];
    const float* fc1_b  = (const float*)d_in[13];
    const float* fc11_w = (const float*)d_in[14];
    const float* fc11_b = (const float*)d_in[15];
    const float* fc12_w = (const float*)d_in[16];
    const float* fc12_b = (const float*)d_in[17];
    const float* fc2_w  = (const float*)d_in[18];
    const float* fc2_b  = (const float*)d_in[19];
    const float* fc3_w  = (const float*)d_in[20];
    const float* fc3_b  = (const float*)d_in[21];

    float* out = (float*)d_out;

    __half *hx, *hG, *hw, *th, *tTh, *zh, *p1h, *p2h, *p3h, *p4h, *n1h, *n2h;
    float *n1, *n2, *R11, *B12, *R22, *B21, *dot, *partR, *partC;
    cudaGetSymbolAddress((void**)&hx,  g_hx);
    cudaGetSymbolAddress((void**)&hG,  g_hG);
    cudaGetSymbolAddress((void**)&hw,  g_hw);
    cudaGetSymbolAddress((void**)&th,  g_th);
    cudaGetSymbolAddress((void**)&tTh, g_tTh);
    cudaGetSymbolAddress((void**)&zh,  g_zh);
    cudaGetSymbolAddress((void**)&p1h, g_p1h);
    cudaGetSymbolAddress((void**)&p2h, g_p2h);
    cudaGetSymbolAddress((void**)&p3h, g_p3h);
    cudaGetSymbolAddress((void**)&p4h, g_p4h);
    cudaGetSymbolAddress((void**)&n1h, g_n1h);
    cudaGetSymbolAddress((void**)&n2h, g_n2h);
    cudaGetSymbolAddress((void**)&n1,  g_n1);
    cudaGetSymbolAddress((void**)&n2,  g_n2);
    cudaGetSymbolAddress((void**)&R11, g_R11);
    cudaGetSymbolAddress((void**)&B12, g_B12);
    cudaGetSymbolAddress((void**)&R22, g_R22);
    cudaGetSymbolAddress((void**)&B21, g_B21);
    cudaGetSymbolAddress((void**)&dot, g_dot);
    cudaGetSymbolAddress((void**)&partR, g_partR);
    cudaGetSymbolAddress((void**)&partC, g_partC);

    // --- convert inputs to fp16 (G pre-scaled by 4096 to stay in normal range) ---
    launch_cvt(x[0], hx,            1.0f,    NN * INF);
    launch_cvt(x[1], hx + NN * INF, 1.0f,    NN * INF);
    launch_cvt(G[0], hG,            4096.0f, NN * NN);
    launch_cvt(G[1], hG + NN * NN,  4096.0f, NN * NN);
    // --- transpose+convert weights: [K,N] fp32 -> [N,K] fp16 ---
    launch_cvtT(Wa[0],  hw + OFF_W1A,  INF, HH);
    launch_cvtT(Wb[0],  hw + OFF_W1B,  HH,  HH);
    launch_cvtT(Wa[1],  hw + OFF_W2A,  INF, HH);
    launch_cvtT(Wb[1],  hw + OFF_W2B,  HH,  HH);
    launch_cvtT(fc1_w,  hw + OFF_FC1,  2 * HH, HH);
    launch_cvtT(fc11_w, hw + OFF_FC11, HH,  512);
    launch_cvtT(fc12_w, hw + OFF_FC12, 512, 256);
    launch_cvtT(fc2_w,  hw + OFF_FC2,  256, 512);
    launch_cvtT(fc3_w,  hw + OFF_FC3,  512, 256);

    const float INV = 1.0f / 4096.0f;
    const size_t ZV = (size_t)NN * 2 * HH;   // per-view z size

    // T1 = x@Wa + ba  (both views)
    launch_hgemm(0,
        { hx,            hw + OFF_W1A, ba[0], nullptr, th },
        { hx + NN * INF, hw + OFF_W2A, ba[1], nullptr, th + NN * HH },
        INF, INF, 1.f, HH, NN, HH, INF);
    transposeh_kernel<<<dim3(HH / 32, NN / 32, 2), dim3(32, 8)>>>(th, tTh, NN, HH);
    // H1 = leaky(G@T1): fp32 -> z slices of out, fp16 -> zh
    launch_hgemm(1,
        { hG,           tTh,           nullptr, out,      zh },
        { hG + NN * NN, tTh + NN * HH, nullptr, out + ZV, zh + ZV },
        NN, NN, INV, 2 * HH, NN, HH, NN);
    // T2 = H1@Wb + bb
    launch_hgemm(0,
        { zh,      hw + OFF_W1B, bb[0], nullptr, th },
        { zh + ZV, hw + OFF_W2B, bb[1], nullptr, th + NN * HH },
        2 * HH, HH, 1.f, HH, NN, HH, HH);
    transposeh_kernel<<<dim3(HH / 32, NN / 32, 2), dim3(32, 8)>>>(th, tTh, NN, HH);
    // H2 = leaky(G@T2)
    launch_hgemm(1,
        { hG,           tTh,           nullptr, out + HH,      zh + HH },
        { hG + NN * NN, tTh + NN * HH, nullptr, out + ZV + HH, zh + ZV + HH },
        NN, NN, INV, 2 * HH, NN, HH, NN);

    // --- projection head (weights shared across views) ---
    launch_hgemm(2,
        { zh,      hw + OFF_FC1, fc1_b, nullptr, p1h },
        { zh + ZV, hw + OFF_FC1, fc1_b, nullptr, p1h + NN * HH },
        2 * HH, 2 * HH, 1.f, HH, NN, HH, 2 * HH);
    launch_hgemm(2,
        { p1h,           hw + OFF_FC11, fc11_b, nullptr, p2h },
        { p1h + NN * HH, hw + OFF_FC11, fc11_b, nullptr, p2h + NN * 512 },
        HH, HH, 1.f, 512, NN, 512, HH);
    launch_hgemm(2,
        { p2h,            hw + OFF_FC12, fc12_b, nullptr, p3h },
        { p2h + NN * 512, hw + OFF_FC12, fc12_b, nullptr, p3h + NN * 256 },
        512, 512, 1.f, 256, NN, 256, 512);
    launch_hgemm(2,
        { p3h,            hw + OFF_FC2, fc2_b, nullptr, p4h },
        { p3h + NN * 256, hw + OFF_FC2, fc2_b, nullptr, p4h + NN * 512 },
        256, 256, 1.f, 512, NN, 512, 256);
    launch_hgemm(0,
        { p4h,            hw + OFF_FC3, fc3_b, n1, nullptr },
        { p4h + NN * 512, hw + OFF_FC3, fc3_b, n2, nullptr },
        512, 512, 1.f, 256, NN, 256, 512);

    normalize_kernel<<<NN / 8, 256>>>(n1, n1h, NN, PP);
    normalize_kernel<<<NN / 8, 256>>>(n2, n2h, NN, PP);

    dim3 egrid(32, 32), eblock(256);
    cudaFuncSetAttribute(expsum_h_kernel, cudaFuncAttributeMaxDynamicSharedMemorySize, HG_SMEM_BYTES);
    expsum_h_kernel<<<egrid, eblock, HG_SMEM_BYTES>>>(n1h, n1h, partR, nullptr, NN, PP);
    reduce32_kernel<<<NN / 256, 256>>>(partR, R11, NN);
    expsum_h_kernel<<<egrid, eblock, HG_SMEM_BYTES>>>(n2h, n2h, partR, nullptr, NN, PP);
    reduce32_kernel<<<NN / 256, 256>>>(partR, R22, NN);
    expsum_h_kernel<<<egrid, eblock, HG_SMEM_BYTES>>>(n1h, n2h, partR, partC, NN, PP);
    reduce32_kernel<<<NN / 256, 256>>>(partR, B12, NN);
    reduce32_kernel<<<NN / 256, 256>>>(partC, B21, NN);

    rowdot_kernel<<<NN / 8, 256>>>(n1, n2, dot, NN, PP);

    loss_kernel<<<1, 256>>>(R11, B12, R22, B21, dot, out + (out_size - 1), NN);
}